// round 1
// baseline (speedup 1.0000x reference)
#include <cuda_runtime.h>
#include <cstdint>
#include <cstddef>

#define TT 2048
#define BB 16
#define DD 64
#define EE 512
#define NN (BB*TT)

// Scratch (static device globals — no runtime allocation allowed)
__device__ float g_q[(size_t)NN * DD];          // 8 MB   projected q
__device__ float g_S[(size_t)BB * TT * TT];     // 256 MB scores S = qq^T/8
__device__ float g_m[NN];                       // row max
__device__ float g_iz[NN];                      // 1/rowsum(exp)

typedef unsigned long long ull;

__device__ __forceinline__ ull pk2(float x, float y) {
    ull r; asm("mov.b64 %0,{%1,%2};" : "=l"(r) : "f"(x), "f"(y)); return r;
}
__device__ __forceinline__ void fma2(ull &d, ull a, ull b) {
    asm("fma.rn.f32x2 %0,%1,%2,%0;" : "+l"(d) : "l"(a), "l"(b));
}
__device__ __forceinline__ void upk(ull v, float &x, float &y) {
    asm("mov.b64 {%0,%1},%2;" : "=f"(x), "=f"(y) : "l"(v));
}

// ---------------------------------------------------------------------------
// K1: q = x @ Wq + bq    (x: [N,512], Wq: [512,64])
// block: 128 threads, tile 128 rows x 64 cols, micro 8x8, k-chunks of 64
// ---------------------------------------------------------------------------
__global__ __launch_bounds__(128) void k1_proj(
    const float* __restrict__ x, const float* __restrict__ Wq,
    const float* __restrict__ bq)
{
    extern __shared__ float sm[];
    float (*xsT)[132] = (float(*)[132])sm;            // [64][132] x chunk, k-major
    float (*ws)[68]   = (float(*)[68])(sm + 64*132);  // [64][68]  Wq chunk
    float *bs = sm + 64*132 + 64*68;

    const int tid = threadIdx.x;
    const int r0 = blockIdx.x * 128;
    if (tid < 64) bs[tid] = bq[tid];

    const int tx = tid & 7, ty = tid >> 3;            // cols {tx*4, 32+tx*4}, rows ty*8..
    ull acc[8][4];
    #pragma unroll
    for (int r = 0; r < 8; r++)
        #pragma unroll
        for (int c = 0; c < 4; c++) acc[r][c] = 0ull;

    for (int kc = 0; kc < EE; kc += 64) {
        __syncthreads();
        #pragma unroll
        for (int idx = tid; idx < 1024; idx += 128) {
            int k = idx >> 4, qd = idx & 15;
            ((float4*)&ws[k][0])[qd] = ((const float4*)(Wq + (size_t)(kc + k) * DD))[qd];
        }
        const float* xr = x + (size_t)(r0 + tid) * EE + kc;
        #pragma unroll
        for (int u = 0; u < 16; u++) {
            float4 v = *(const float4*)(xr + u * 4);
            xsT[u*4+0][tid] = v.x; xsT[u*4+1][tid] = v.y;
            xsT[u*4+2][tid] = v.z; xsT[u*4+3][tid] = v.w;
        }
        __syncthreads();
        #pragma unroll 8
        for (int k = 0; k < 64; k++) {
            float4 a0 = *(const float4*)&xsT[k][ty*8];
            float4 a1 = *(const float4*)&xsT[k][ty*8+4];
            float4 b0 = *(const float4*)&ws[k][tx*4];
            float4 b1 = *(const float4*)&ws[k][32 + tx*4];
            ull bb0 = pk2(b0.x,b0.y), bb1 = pk2(b0.z,b0.w);
            ull bb2 = pk2(b1.x,b1.y), bb3 = pk2(b1.z,b1.w);
            float av[8] = {a0.x,a0.y,a0.z,a0.w,a1.x,a1.y,a1.z,a1.w};
            #pragma unroll
            for (int r = 0; r < 8; r++) {
                ull ar = pk2(av[r], av[r]);
                fma2(acc[r][0], ar, bb0); fma2(acc[r][1], ar, bb1);
                fma2(acc[r][2], ar, bb2); fma2(acc[r][3], ar, bb3);
            }
        }
    }
    #pragma unroll
    for (int r = 0; r < 8; r++) {
        float f[8];
        upk(acc[r][0], f[0], f[1]); upk(acc[r][1], f[2], f[3]);
        upk(acc[r][2], f[4], f[5]); upk(acc[r][3], f[6], f[7]);
        int row = r0 + ty*8 + r;
        float4 v0 = make_float4(f[0]+bs[tx*4+0], f[1]+bs[tx*4+1],
                                f[2]+bs[tx*4+2], f[3]+bs[tx*4+3]);
        float4 v1 = make_float4(f[4]+bs[32+tx*4+0], f[5]+bs[32+tx*4+1],
                                f[6]+bs[32+tx*4+2], f[7]+bs[32+tx*4+3]);
        *(float4*)(g_q + (size_t)row * DD + tx*4) = v0;
        *(float4*)(g_q + (size_t)row * DD + 32 + tx*4) = v1;
    }
}

// ---------------------------------------------------------------------------
// K2: S[b] = (q/8) @ q^T, upper-triangular 128x128 tiles + mirror writes
// grid (136, 16), 256 threads, micro 8x8
// ---------------------------------------------------------------------------
__global__ __launch_bounds__(256) void k2_sgemm()
{
    extern __shared__ float sm[];
    float (*qjT)[132] = (float(*)[132])sm;              // scaled by 1/8
    float (*qiT)[132] = (float(*)[132])(sm + 64*132);

    const int b = blockIdx.y;
    int jy = 0, rem = blockIdx.x;
    while (rem >= 16 - jy) { rem -= 16 - jy; jy++; }
    const int ix = jy + rem;
    const int j0 = jy * 128, i0 = ix * 128;

    const float* qb = g_q + (size_t)b * TT * DD;
    const int tid = threadIdx.x;
    {
        const int r = tid & 127;
        const int u0 = (tid >> 7) * 8;
        const float* qjrow = qb + (size_t)(j0 + r) * DD;
        const float* qirow = qb + (size_t)(i0 + r) * DD;
        #pragma unroll
        for (int u = 0; u < 8; u++) {
            float4 v = *(const float4*)(qjrow + (u0+u)*4);
            qjT[(u0+u)*4+0][r] = v.x*0.125f; qjT[(u0+u)*4+1][r] = v.y*0.125f;
            qjT[(u0+u)*4+2][r] = v.z*0.125f; qjT[(u0+u)*4+3][r] = v.w*0.125f;
            float4 w = *(const float4*)(qirow + (u0+u)*4);
            qiT[(u0+u)*4+0][r] = w.x; qiT[(u0+u)*4+1][r] = w.y;
            qiT[(u0+u)*4+2][r] = w.z; qiT[(u0+u)*4+3][r] = w.w;
        }
    }
    __syncthreads();

    const int tx = tid & 15, ty = tid >> 4;   // cols {tx*4, 64+tx*4}, rows ty*8..
    ull acc[8][4];
    #pragma unroll
    for (int r = 0; r < 8; r++)
        #pragma unroll
        for (int c = 0; c < 4; c++) acc[r][c] = 0ull;

    #pragma unroll 8
    for (int k = 0; k < 64; k++) {
        float4 a0 = *(const float4*)&qjT[k][ty*8];
        float4 a1 = *(const float4*)&qjT[k][ty*8+4];
        float4 b0 = *(const float4*)&qiT[k][tx*4];
        float4 b1 = *(const float4*)&qiT[k][64 + tx*4];
        ull bb0 = pk2(b0.x,b0.y), bb1 = pk2(b0.z,b0.w);
        ull bb2 = pk2(b1.x,b1.y), bb3 = pk2(b1.z,b1.w);
        float av[8] = {a0.x,a0.y,a0.z,a0.w,a1.x,a1.y,a1.z,a1.w};
        #pragma unroll
        for (int r = 0; r < 8; r++) {
            ull ar = pk2(av[r], av[r]);
            fma2(acc[r][0], ar, bb0); fma2(acc[r][1], ar, bb1);
            fma2(acc[r][2], ar, bb2); fma2(acc[r][3], ar, bb3);
        }
    }

    float accf[8][8];
    #pragma unroll
    for (int r = 0; r < 8; r++) {
        upk(acc[r][0], accf[r][0], accf[r][1]);
        upk(acc[r][1], accf[r][2], accf[r][3]);
        upk(acc[r][2], accf[r][4], accf[r][5]);
        upk(acc[r][3], accf[r][6], accf[r][7]);
    }

    float* Sb = g_S + (size_t)b * TT * TT;
    #pragma unroll
    for (int r = 0; r < 8; r++) {
        size_t ro = (size_t)(j0 + ty*8 + r) * TT;
        *(float4*)(Sb + ro + i0 + tx*4)      = make_float4(accf[r][0],accf[r][1],accf[r][2],accf[r][3]);
        *(float4*)(Sb + ro + i0 + 64 + tx*4) = make_float4(accf[r][4],accf[r][5],accf[r][6],accf[r][7]);
    }
    if (ix != jy) {
        #pragma unroll
        for (int c = 0; c < 8; c++) {
            int gi = i0 + (c < 4 ? tx*4 + c : 64 + tx*4 + (c - 4));
            size_t ro = (size_t)gi * TT + j0 + ty*8;
            *(float4*)(Sb + ro)     = make_float4(accf[0][c],accf[1][c],accf[2][c],accf[3][c]);
            *(float4*)(Sb + ro + 4) = make_float4(accf[4][c],accf[5][c],accf[6][c],accf[7][c]);
        }
    }
}

// ---------------------------------------------------------------------------
// K3: per-row max & 1/sumexp.  One warp per row, row held in registers.
// ---------------------------------------------------------------------------
__global__ __launch_bounds__(256) void k3_stats()
{
    const int n = blockIdx.x * 8 + (threadIdx.x >> 5);
    const int lane = threadIdx.x & 31;
    const float* Sr = g_S + (size_t)n * TT;

    float4 v[16];
    float m = -3.0e38f;
    #pragma unroll
    for (int u = 0; u < 16; u++) {
        v[u] = *(const float4*)(Sr + (size_t)(u*32 + lane) * 4);
        m = fmaxf(m, fmaxf(fmaxf(v[u].x, v[u].y), fmaxf(v[u].z, v[u].w)));
    }
    #pragma unroll
    for (int o = 16; o; o >>= 1) m = fmaxf(m, __shfl_xor_sync(0xffffffffu, m, o));
    float s = 0.f;
    #pragma unroll
    for (int u = 0; u < 16; u++)
        s += __expf(v[u].x - m) + __expf(v[u].y - m) + __expf(v[u].z - m) + __expf(v[u].w - m);
    #pragma unroll
    for (int o = 16; o; o >>= 1) s += __shfl_xor_sync(0xffffffffu, s, o);
    if (lane == 0) { g_m[n] = m; g_iz[n] = 1.0f / s; }
}

// ---------------------------------------------------------------------------
// K4: out[i,d] = sum_j exp(S[i,j]-m_j)*iz_j*q[j,d]
// grid (16 i-tiles, 16 b), 128 threads, tile 128 x 64, micro 8x8, j-chunks 64
// ---------------------------------------------------------------------------
__global__ __launch_bounds__(128) void k4_pv(float* __restrict__ out)
{
    extern __shared__ float sm[];
    float (*pT)[132] = (float(*)[132])sm;              // [64 j][132 i] probs
    float (*qs)[68]  = (float(*)[68])(sm + 64*132);    // [64 j][68 d]
    float* ms = sm + 64*132 + 64*68;
    float* zs = ms + 64;

    const int b = blockIdx.y;
    const int i0 = blockIdx.x * 128;
    const float* Sb = g_S + (size_t)b * TT * TT;
    const float* qb = g_q + (size_t)b * TT * DD;
    const int tid = threadIdx.x;
    const int tx = tid & 7, ty = tid >> 3;   // cols {tx*4, 32+tx*4}, rows ty*8..

    ull acc[8][4];
    #pragma unroll
    for (int r = 0; r < 8; r++)
        #pragma unroll
        for (int c = 0; c < 4; c++) acc[r][c] = 0ull;

    for (int jc = 0; jc < TT; jc += 64) {
        __syncthreads();
        if (tid < 64) {
            ms[tid] = g_m[b*TT + jc + tid];
            zs[tid] = g_iz[b*TT + jc + tid];
        }
        #pragma unroll
        for (int idx = tid; idx < 1024; idx += 128) {
            int j = idx >> 4, qd = idx & 15;
            ((float4*)&qs[j][0])[qd] = ((const float4*)(qb + (size_t)(jc + j) * DD))[qd];
        }
        __syncthreads();
        {
            const float* srow = Sb + (size_t)(i0 + tid) * TT + jc;
            #pragma unroll
            for (int u = 0; u < 16; u++) {
                float4 v = *(const float4*)(srow + u*4);
                pT[u*4+0][tid] = __expf(v.x - ms[u*4+0]) * zs[u*4+0];
                pT[u*4+1][tid] = __expf(v.y - ms[u*4+1]) * zs[u*4+1];
                pT[u*4+2][tid] = __expf(v.z - ms[u*4+2]) * zs[u*4+2];
                pT[u*4+3][tid] = __expf(v.w - ms[u*4+3]) * zs[u*4+3];
            }
        }
        __syncthreads();
        #pragma unroll 8
        for (int k = 0; k < 64; k++) {
            float4 a0 = *(const float4*)&pT[k][ty*8];
            float4 a1 = *(const float4*)&pT[k][ty*8+4];
            float4 b0 = *(const float4*)&qs[k][tx*4];
            float4 b1 = *(const float4*)&qs[k][32 + tx*4];
            ull bb0 = pk2(b0.x,b0.y), bb1 = pk2(b0.z,b0.w);
            ull bb2 = pk2(b1.x,b1.y), bb3 = pk2(b1.z,b1.w);
            float av[8] = {a0.x,a0.y,a0.z,a0.w,a1.x,a1.y,a1.z,a1.w};
            #pragma unroll
            for (int r = 0; r < 8; r++) {
                ull ar = pk2(av[r], av[r]);
                fma2(acc[r][0], ar, bb0); fma2(acc[r][1], ar, bb1);
                fma2(acc[r][2], ar, bb2); fma2(acc[r][3], ar, bb3);
            }
        }
    }

    #pragma unroll
    for (int r = 0; r < 8; r++) {
        float f[8];
        upk(acc[r][0], f[0], f[1]); upk(acc[r][1], f[2], f[3]);
        upk(acc[r][2], f[4], f[5]); upk(acc[r][3], f[6], f[7]);
        int row = i0 + ty*8 + r;
        *(float4*)(out + ((size_t)b*TT + row) * DD + tx*4)      = make_float4(f[0],f[1],f[2],f[3]);
        *(float4*)(out + ((size_t)b*TT + row) * DD + 32 + tx*4) = make_float4(f[4],f[5],f[6],f[7]);
    }
}

// ---------------------------------------------------------------------------
extern "C" void kernel_launch(void* const* d_in, const int* in_sizes, int n_in,
                              void* d_out, int out_size)
{
    const float* x  = (const float*)d_in[0];
    const float* Wq = (const float*)d_in[1];
    const float* bq = (const float*)d_in[2];
    float* out = (float*)d_out;

    const int smem1 = (64*132 + 64*68 + 64)  * 4;   // 51456
    const int smem2 = (2*64*132)             * 4;   // 67584
    const int smem4 = (64*132 + 64*68 + 128) * 4;   // 51712

    cudaFuncSetAttribute(k1_proj,  cudaFuncAttributeMaxDynamicSharedMemorySize, smem1);
    cudaFuncSetAttribute(k2_sgemm, cudaFuncAttributeMaxDynamicSharedMemorySize, smem2);
    cudaFuncSetAttribute(k4_pv,    cudaFuncAttributeMaxDynamicSharedMemorySize, smem4);

    k1_proj<<<NN/128, 128, smem1>>>(x, Wq, bq);
    k2_sgemm<<<dim3(136, BB), 256, smem2>>>();
    k3_stats<<<NN/8, 256>>>();
    k4_pv<<<dim3(TT/128, BB), 128, smem4>>>(out);
}

// round 2
// speedup vs baseline: 1.0001x; 1.0001x over previous
#include <cuda_runtime.h>
#include <cstdint>
#include <cstddef>

#define TT 2048
#define BB 16
#define DD 64
#define EE 512
#define NN (BB*TT)

// Scratch (static device globals — no runtime allocation allowed)
__device__ float g_q[(size_t)NN * DD];          // 8 MB   projected q
__device__ float g_S[(size_t)BB * TT * TT];     // 256 MB scores S = qq^T/8
__device__ float g_m[NN];                       // row max
__device__ float g_iz[NN];                      // 1/rowsum(exp)

typedef unsigned long long ull;

__device__ __forceinline__ ull pk2(float x, float y) {
    ull r; asm("mov.b64 %0,{%1,%2};" : "=l"(r) : "f"(x), "f"(y)); return r;
}
__device__ __forceinline__ void fma2(ull &d, ull a, ull b) {
    asm("fma.rn.f32x2 %0,%1,%2,%0;" : "+l"(d) : "l"(a), "l"(b));
}
__device__ __forceinline__ void upk(ull v, float &x, float &y) {
    asm("mov.b64 {%0,%1},%2;" : "=f"(x), "=f"(y) : "l"(v));
}

// ---------------------------------------------------------------------------
// K1: q = x @ Wq + bq    (x: [N,512], Wq: [512,64])
// block: 128 threads, tile 128 rows x 64 cols, micro 8x8, k-chunks of 64
// ---------------------------------------------------------------------------
__global__ __launch_bounds__(128) void k1_proj(
    const float* __restrict__ x, const float* __restrict__ Wq,
    const float* __restrict__ bq)
{
    extern __shared__ float sm[];
    float (*xsT)[132] = (float(*)[132])sm;            // [64][132] x chunk, k-major
    float (*ws)[68]   = (float(*)[68])(sm + 64*132);  // [64][68]  Wq chunk
    float *bs = sm + 64*132 + 64*68;

    const int tid = threadIdx.x;
    const int r0 = blockIdx.x * 128;
    if (tid < 64) bs[tid] = bq[tid];

    const int tx = tid & 7, ty = tid >> 3;            // cols {tx*4, 32+tx*4}, rows ty*8..
    ull acc[8][4];
    #pragma unroll
    for (int r = 0; r < 8; r++)
        #pragma unroll
        for (int c = 0; c < 4; c++) acc[r][c] = 0ull;

    for (int kc = 0; kc < EE; kc += 64) {
        __syncthreads();
        #pragma unroll
        for (int idx = tid; idx < 1024; idx += 128) {
            int k = idx >> 4, qd = idx & 15;
            ((float4*)&ws[k][0])[qd] = ((const float4*)(Wq + (size_t)(kc + k) * DD))[qd];
        }
        const float* xr = x + (size_t)(r0 + tid) * EE + kc;
        #pragma unroll
        for (int u = 0; u < 16; u++) {
            float4 v = *(const float4*)(xr + u * 4);
            xsT[u*4+0][tid] = v.x; xsT[u*4+1][tid] = v.y;
            xsT[u*4+2][tid] = v.z; xsT[u*4+3][tid] = v.w;
        }
        __syncthreads();
        #pragma unroll 8
        for (int k = 0; k < 64; k++) {
            float4 a0 = *(const float4*)&xsT[k][ty*8];
            float4 a1 = *(const float4*)&xsT[k][ty*8+4];
            float4 b0 = *(const float4*)&ws[k][tx*4];
            float4 b1 = *(const float4*)&ws[k][32 + tx*4];
            ull bb0 = pk2(b0.x,b0.y), bb1 = pk2(b0.z,b0.w);
            ull bb2 = pk2(b1.x,b1.y), bb3 = pk2(b1.z,b1.w);
            float av[8] = {a0.x,a0.y,a0.z,a0.w,a1.x,a1.y,a1.z,a1.w};
            #pragma unroll
            for (int r = 0; r < 8; r++) {
                ull ar = pk2(av[r], av[r]);
                fma2(acc[r][0], ar, bb0); fma2(acc[r][1], ar, bb1);
                fma2(acc[r][2], ar, bb2); fma2(acc[r][3], ar, bb3);
            }
        }
    }
    #pragma unroll
    for (int r = 0; r < 8; r++) {
        float f[8];
        upk(acc[r][0], f[0], f[1]); upk(acc[r][1], f[2], f[3]);
        upk(acc[r][2], f[4], f[5]); upk(acc[r][3], f[6], f[7]);
        int row = r0 + ty*8 + r;
        float4 v0 = make_float4(f[0]+bs[tx*4+0], f[1]+bs[tx*4+1],
                                f[2]+bs[tx*4+2], f[3]+bs[tx*4+3]);
        float4 v1 = make_float4(f[4]+bs[32+tx*4+0], f[5]+bs[32+tx*4+1],
                                f[6]+bs[32+tx*4+2], f[7]+bs[32+tx*4+3]);
        *(float4*)(g_q + (size_t)row * DD + tx*4) = v0;
        *(float4*)(g_q + (size_t)row * DD + 32 + tx*4) = v1;
    }
}

// ---------------------------------------------------------------------------
// K2: S[b] = (q/8) @ q^T, upper-triangular 128x128 tiles + mirror writes
// grid (136, 16), 256 threads, micro 8x8
// ---------------------------------------------------------------------------
__global__ __launch_bounds__(256) void k2_sgemm()
{
    extern __shared__ float sm[];
    float (*qjT)[132] = (float(*)[132])sm;              // scaled by 1/8
    float (*qiT)[132] = (float(*)[132])(sm + 64*132);

    const int b = blockIdx.y;
    int jy = 0, rem = blockIdx.x;
    while (rem >= 16 - jy) { rem -= 16 - jy; jy++; }
    const int ix = jy + rem;
    const int j0 = jy * 128, i0 = ix * 128;

    const float* qb = g_q + (size_t)b * TT * DD;
    const int tid = threadIdx.x;
    {
        const int r = tid & 127;
        const int u0 = (tid >> 7) * 8;
        const float* qjrow = qb + (size_t)(j0 + r) * DD;
        const float* qirow = qb + (size_t)(i0 + r) * DD;
        #pragma unroll
        for (int u = 0; u < 8; u++) {
            float4 v = *(const float4*)(qjrow + (u0+u)*4);
            qjT[(u0+u)*4+0][r] = v.x*0.125f; qjT[(u0+u)*4+1][r] = v.y*0.125f;
            qjT[(u0+u)*4+2][r] = v.z*0.125f; qjT[(u0+u)*4+3][r] = v.w*0.125f;
            float4 w = *(const float4*)(qirow + (u0+u)*4);
            qiT[(u0+u)*4+0][r] = w.x; qiT[(u0+u)*4+1][r] = w.y;
            qiT[(u0+u)*4+2][r] = w.z; qiT[(u0+u)*4+3][r] = w.w;
        }
    }
    __syncthreads();

    const int tx = tid & 15, ty = tid >> 4;   // cols {tx*4, 64+tx*4}, rows ty*8..
    ull acc[8][4];
    #pragma unroll
    for (int r = 0; r < 8; r++)
        #pragma unroll
        for (int c = 0; c < 4; c++) acc[r][c] = 0ull;

    #pragma unroll 8
    for (int k = 0; k < 64; k++) {
        float4 a0 = *(const float4*)&qjT[k][ty*8];
        float4 a1 = *(const float4*)&qjT[k][ty*8+4];
        float4 b0 = *(const float4*)&qiT[k][tx*4];
        float4 b1 = *(const float4*)&qiT[k][64 + tx*4];
        ull bb0 = pk2(b0.x,b0.y), bb1 = pk2(b0.z,b0.w);
        ull bb2 = pk2(b1.x,b1.y), bb3 = pk2(b1.z,b1.w);
        float av[8] = {a0.x,a0.y,a0.z,a0.w,a1.x,a1.y,a1.z,a1.w};
        #pragma unroll
        for (int r = 0; r < 8; r++) {
            ull ar = pk2(av[r], av[r]);
            fma2(acc[r][0], ar, bb0); fma2(acc[r][1], ar, bb1);
            fma2(acc[r][2], ar, bb2); fma2(acc[r][3], ar, bb3);
        }
    }

    float accf[8][8];
    #pragma unroll
    for (int r = 0; r < 8; r++) {
        upk(acc[r][0], accf[r][0], accf[r][1]);
        upk(acc[r][1], accf[r][2], accf[r][3]);
        upk(acc[r][2], accf[r][4], accf[r][5]);
        upk(acc[r][3], accf[r][6], accf[r][7]);
    }

    float* Sb = g_S + (size_t)b * TT * TT;
    #pragma unroll
    for (int r = 0; r < 8; r++) {
        size_t ro = (size_t)(j0 + ty*8 + r) * TT;
        *(float4*)(Sb + ro + i0 + tx*4)      = make_float4(accf[r][0],accf[r][1],accf[r][2],accf[r][3]);
        *(float4*)(Sb + ro + i0 + 64 + tx*4) = make_float4(accf[r][4],accf[r][5],accf[r][6],accf[r][7]);
    }
    if (ix != jy) {
        #pragma unroll
        for (int c = 0; c < 8; c++) {
            int gi = i0 + (c < 4 ? tx*4 + c : 64 + tx*4 + (c - 4));
            size_t ro = (size_t)gi * TT + j0 + ty*8;
            *(float4*)(Sb + ro)     = make_float4(accf[0][c],accf[1][c],accf[2][c],accf[3][c]);
            *(float4*)(Sb + ro + 4) = make_float4(accf[4][c],accf[5][c],accf[6][c],accf[7][c]);
        }
    }
}

// ---------------------------------------------------------------------------
// K3: per-row max & 1/sumexp.  One warp per row, row held in registers.
// ---------------------------------------------------------------------------
__global__ __launch_bounds__(256) void k3_stats()
{
    const int n = blockIdx.x * 8 + (threadIdx.x >> 5);
    const int lane = threadIdx.x & 31;
    const float* Sr = g_S + (size_t)n * TT;

    float4 v[16];
    float m = -3.0e38f;
    #pragma unroll
    for (int u = 0; u < 16; u++) {
        v[u] = *(const float4*)(Sr + (size_t)(u*32 + lane) * 4);
        m = fmaxf(m, fmaxf(fmaxf(v[u].x, v[u].y), fmaxf(v[u].z, v[u].w)));
    }
    #pragma unroll
    for (int o = 16; o; o >>= 1) m = fmaxf(m, __shfl_xor_sync(0xffffffffu, m, o));
    float s = 0.f;
    #pragma unroll
    for (int u = 0; u < 16; u++)
        s += __expf(v[u].x - m) + __expf(v[u].y - m) + __expf(v[u].z - m) + __expf(v[u].w - m);
    #pragma unroll
    for (int o = 16; o; o >>= 1) s += __shfl_xor_sync(0xffffffffu, s, o);
    if (lane == 0) { g_m[n] = m; g_iz[n] = 1.0f / s; }
}

// ---------------------------------------------------------------------------
// K4: out[i,d] = sum_j exp(S[i,j]-m_j)*iz_j*q[j,d]
// grid (16 i-tiles, 16 b), 128 threads, tile 128 x 64, micro 8x8, j-chunks 64
// ---------------------------------------------------------------------------
__global__ __launch_bounds__(128) void k4_pv(float* __restrict__ out)
{
    extern __shared__ float sm[];
    float (*pT)[132] = (float(*)[132])sm;              // [64 j][132 i] probs
    float (*qs)[68]  = (float(*)[68])(sm + 64*132);    // [64 j][68 d]
    float* ms = sm + 64*132 + 64*68;
    float* zs = ms + 64;

    const int b = blockIdx.y;
    const int i0 = blockIdx.x * 128;
    const float* Sb = g_S + (size_t)b * TT * TT;
    const float* qb = g_q + (size_t)b * TT * DD;
    const int tid = threadIdx.x;
    const int tx = tid & 7, ty = tid >> 3;   // cols {tx*4, 32+tx*4}, rows ty*8..

    ull acc[8][4];
    #pragma unroll
    for (int r = 0; r < 8; r++)
        #pragma unroll
        for (int c = 0; c < 4; c++) acc[r][c] = 0ull;

    for (int jc = 0; jc < TT; jc += 64) {
        __syncthreads();
        if (tid < 64) {
            ms[tid] = g_m[b*TT + jc + tid];
            zs[tid] = g_iz[b*TT + jc + tid];
        }
        #pragma unroll
        for (int idx = tid; idx < 1024; idx += 128) {
            int j = idx >> 4, qd = idx & 15;
            ((float4*)&qs[j][0])[qd] = ((const float4*)(qb + (size_t)(jc + j) * DD))[qd];
        }
        __syncthreads();
        {
            const float* srow = Sb + (size_t)(i0 + tid) * TT + jc;
            #pragma unroll
            for (int u = 0; u < 16; u++) {
                float4 v = *(const float4*)(srow + u*4);
                pT[u*4+0][tid] = __expf(v.x - ms[u*4+0]) * zs[u*4+0];
                pT[u*4+1][tid] = __expf(v.y - ms[u*4+1]) * zs[u*4+1];
                pT[u*4+2][tid] = __expf(v.z - ms[u*4+2]) * zs[u*4+2];
                pT[u*4+3][tid] = __expf(v.w - ms[u*4+3]) * zs[u*4+3];
            }
        }
        __syncthreads();
        #pragma unroll 8
        for (int k = 0; k < 64; k++) {
            float4 a0 = *(const float4*)&pT[k][ty*8];
            float4 a1 = *(const float4*)&pT[k][ty*8+4];
            float4 b0 = *(const float4*)&qs[k][tx*4];
            float4 b1 = *(const float4*)&qs[k][32 + tx*4];
            ull bb0 = pk2(b0.x,b0.y), bb1 = pk2(b0.z,b0.w);
            ull bb2 = pk2(b1.x,b1.y), bb3 = pk2(b1.z,b1.w);
            float av[8] = {a0.x,a0.y,a0.z,a0.w,a1.x,a1.y,a1.z,a1.w};
            #pragma unroll
            for (int r = 0; r < 8; r++) {
                ull ar = pk2(av[r], av[r]);
                fma2(acc[r][0], ar, bb0); fma2(acc[r][1], ar, bb1);
                fma2(acc[r][2], ar, bb2); fma2(acc[r][3], ar, bb3);
            }
        }
    }

    #pragma unroll
    for (int r = 0; r < 8; r++) {
        float f[8];
        upk(acc[r][0], f[0], f[1]); upk(acc[r][1], f[2], f[3]);
        upk(acc[r][2], f[4], f[5]); upk(acc[r][3], f[6], f[7]);
        int row = i0 + ty*8 + r;
        *(float4*)(out + ((size_t)b*TT + row) * DD + tx*4)      = make_float4(f[0],f[1],f[2],f[3]);
        *(float4*)(out + ((size_t)b*TT + row) * DD + 32 + tx*4) = make_float4(f[4],f[5],f[6],f[7]);
    }
}

// ---------------------------------------------------------------------------
extern "C" void kernel_launch(void* const* d_in, const int* in_sizes, int n_in,
                              void* d_out, int out_size)
{
    const float* x  = (const float*)d_in[0];
    const float* Wq = (const float*)d_in[1];
    const float* bq = (const float*)d_in[2];
    float* out = (float*)d_out;

    const int smem1 = (64*132 + 64*68 + 64)  * 4;   // 51456
    const int smem2 = (2*64*132)             * 4;   // 67584
    const int smem4 = (64*132 + 64*68 + 128) * 4;   // 51712

    cudaFuncSetAttribute(k1_proj,  cudaFuncAttributeMaxDynamicSharedMemorySize, smem1);
    cudaFuncSetAttribute(k2_sgemm, cudaFuncAttributeMaxDynamicSharedMemorySize, smem2);
    cudaFuncSetAttribute(k4_pv,    cudaFuncAttributeMaxDynamicSharedMemorySize, smem4);

    k1_proj<<<NN/128, 128, smem1>>>(x, Wq, bq);
    k2_sgemm<<<dim3(136, BB), 256, smem2>>>();
    k3_stats<<<NN/8, 256>>>();
    k4_pv<<<dim3(TT/128, BB), 128, smem4>>>(out);
}

// round 5
// speedup vs baseline: 1.3887x; 1.3885x over previous
#include <cuda_runtime.h>
#include <cuda_bf16.h>
#include <cstdint>
#include <cstddef>

#define TT 2048
#define BB 16
#define DD 64
#define EE 512
#define NN (BB*TT)

// ---------------------------------------------------------------------------
// Global scratch
// ---------------------------------------------------------------------------
__device__ float    g_S[(size_t)BB * TT * TT];   // 256 MB scores S = qq^T/8 (fp32)
__device__ uint16_t g_qh[(size_t)NN * DD];       // q hi  (bf16 bits), row-major [N][64]
__device__ uint16_t g_ql[(size_t)NN * DD];       // q lo
__device__ uint16_t g_qTh[(size_t)NN * DD];      // q^T hi, [b][64][2048]
__device__ uint16_t g_qTl[(size_t)NN * DD];      // q^T lo
__device__ float    g_c[NN];                     // c = rowmax + log(rowsumexp)

typedef unsigned long long ull;

// ---------------------------------------------------------------------------
// helpers
// ---------------------------------------------------------------------------
__device__ __forceinline__ uint32_t smem_u32(const void* p) {
    uint32_t a;
    asm("{ .reg .u64 t; cvta.to.shared.u64 t, %1; cvt.u32.u64 %0, t; }" : "=r"(a) : "l"(p));
    return a;
}
#define SWZ(o) ((o) ^ (((o) >> 3) & 0x70))

#define LDSM4(r0,r1,r2,r3,a) \
    asm volatile("ldmatrix.sync.aligned.m8n8.x4.shared.b16 {%0,%1,%2,%3}, [%4];" \
        : "=r"(r0),"=r"(r1),"=r"(r2),"=r"(r3) : "r"(a))

__device__ __forceinline__ void mma_bf16(float* d, const uint32_t* a,
                                         uint32_t b0, uint32_t b1) {
    asm volatile("mma.sync.aligned.m16n8k16.row.col.f32.bf16.bf16.f32 "
        "{%0,%1,%2,%3}, {%4,%5,%6,%7}, {%8,%9}, {%0,%1,%2,%3};"
        : "+f"(d[0]),"+f"(d[1]),"+f"(d[2]),"+f"(d[3])
        : "r"(a[0]),"r"(a[1]),"r"(a[2]),"r"(a[3]), "r"(b0),"r"(b1));
}

// fp32 packed-FFMA helpers (K1)
__device__ __forceinline__ ull pk2(float x, float y) {
    ull r; asm("mov.b64 %0,{%1,%2};" : "=l"(r) : "f"(x), "f"(y)); return r;
}
__device__ __forceinline__ void fma2(ull &d, ull a, ull b) {
    asm("fma.rn.f32x2 %0,%1,%2,%0;" : "+l"(d) : "l"(a), "l"(b));
}
__device__ __forceinline__ void upk(ull v, float &x, float &y) {
    asm("mov.b64 {%0,%1},%2;" : "=f"(x), "=f"(y) : "l"(v));
}
__device__ __forceinline__ void bfsplit(float v, uint16_t &h, uint16_t &l) {
    __nv_bfloat16 hh = __float2bfloat16(v);
    float r = v - __bfloat162float(hh);
    __nv_bfloat16 ll = __float2bfloat16(r);
    h = __bfloat16_as_ushort(hh);
    l = __bfloat16_as_ushort(ll);
}

// ---------------------------------------------------------------------------
// K1: q = x @ Wq + bq  -> bf16 hi/lo row-major + transposed  (FFMA2 core)
// ---------------------------------------------------------------------------
__global__ __launch_bounds__(128) void k1_proj(
    const float* __restrict__ x, const float* __restrict__ Wq,
    const float* __restrict__ bq)
{
    extern __shared__ float sm[];
    float (*xsT)[132] = (float(*)[132])sm;
    float (*ws)[68]   = (float(*)[68])(sm + 64*132);
    float *bs = sm + 64*132 + 64*68;

    const int tid = threadIdx.x;
    const int r0 = blockIdx.x * 128;
    if (tid < 64) bs[tid] = bq[tid];

    const int tx = tid & 7, ty = tid >> 3;
    ull acc[8][4];
    #pragma unroll
    for (int r = 0; r < 8; r++)
        #pragma unroll
        for (int c = 0; c < 4; c++) acc[r][c] = 0ull;

    for (int kc = 0; kc < EE; kc += 64) {
        __syncthreads();
        #pragma unroll
        for (int idx = tid; idx < 1024; idx += 128) {
            int k = idx >> 4, qd = idx & 15;
            ((float4*)&ws[k][0])[qd] = ((const float4*)(Wq + (size_t)(kc + k) * DD))[qd];
        }
        const float* xr = x + (size_t)(r0 + tid) * EE + kc;
        #pragma unroll
        for (int u = 0; u < 16; u++) {
            float4 v = *(const float4*)(xr + u * 4);
            xsT[u*4+0][tid] = v.x; xsT[u*4+1][tid] = v.y;
            xsT[u*4+2][tid] = v.z; xsT[u*4+3][tid] = v.w;
        }
        __syncthreads();
        #pragma unroll 8
        for (int k = 0; k < 64; k++) {
            float4 a0 = *(const float4*)&xsT[k][ty*8];
            float4 a1 = *(const float4*)&xsT[k][ty*8+4];
            float4 b0 = *(const float4*)&ws[k][tx*4];
            float4 b1 = *(const float4*)&ws[k][32 + tx*4];
            ull bb0 = pk2(b0.x,b0.y), bb1 = pk2(b0.z,b0.w);
            ull bb2 = pk2(b1.x,b1.y), bb3 = pk2(b1.z,b1.w);
            float av[8] = {a0.x,a0.y,a0.z,a0.w,a1.x,a1.y,a1.z,a1.w};
            #pragma unroll
            for (int r = 0; r < 8; r++) {
                ull ar = pk2(av[r], av[r]);
                fma2(acc[r][0], ar, bb0); fma2(acc[r][1], ar, bb1);
                fma2(acc[r][2], ar, bb2); fma2(acc[r][3], ar, bb3);
            }
        }
    }
    __syncthreads();
    float (*qt)[132] = (float(*)[132])sm;   // [d][row_local]
    const int b = r0 >> 11;
    const int t0l = r0 & (TT - 1);

    #pragma unroll
    for (int r = 0; r < 8; r++) {
        float f[8];
        upk(acc[r][0], f[0], f[1]); upk(acc[r][1], f[2], f[3]);
        upk(acc[r][2], f[4], f[5]); upk(acc[r][3], f[6], f[7]);
        const int rl = ty*8 + r;
        const int row = r0 + rl;
        float v[8];
        #pragma unroll
        for (int c = 0; c < 4; c++) {
            v[c]   = f[c]   + bs[tx*4 + c];
            v[4+c] = f[4+c] + bs[32 + tx*4 + c];
        }
        #pragma unroll
        for (int c = 0; c < 4; c++) {
            qt[tx*4 + c][rl]      = v[c];
            qt[32 + tx*4 + c][rl] = v[4+c];
        }
        uint16_t h[8], l[8];
        #pragma unroll
        for (int c = 0; c < 8; c++) bfsplit(v[c], h[c], l[c]);
        uint2 uh0, ul0, uh1, ul1;
        uh0.x = (uint32_t)h[0] | ((uint32_t)h[1] << 16); uh0.y = (uint32_t)h[2] | ((uint32_t)h[3] << 16);
        uh1.x = (uint32_t)h[4] | ((uint32_t)h[5] << 16); uh1.y = (uint32_t)h[6] | ((uint32_t)h[7] << 16);
        ul0.x = (uint32_t)l[0] | ((uint32_t)l[1] << 16); ul0.y = (uint32_t)l[2] | ((uint32_t)l[3] << 16);
        ul1.x = (uint32_t)l[4] | ((uint32_t)l[5] << 16); ul1.y = (uint32_t)l[6] | ((uint32_t)l[7] << 16);
        *(uint2*)(g_qh + (size_t)row*DD + tx*4)      = uh0;
        *(uint2*)(g_qh + (size_t)row*DD + 32 + tx*4) = uh1;
        *(uint2*)(g_ql + (size_t)row*DD + tx*4)      = ul0;
        *(uint2*)(g_ql + (size_t)row*DD + 32 + tx*4) = ul1;
    }
    __syncthreads();
    for (int idx = tid; idx < 64*64; idx += 128) {
        int d = idx >> 6, tp = idx & 63;
        float v0 = qt[d][tp*2], v1 = qt[d][tp*2 + 1];
        uint16_t h0, l0, h1, l1;
        bfsplit(v0, h0, l0); bfsplit(v1, h1, l1);
        size_t off = ((size_t)b*DD + d)*TT + t0l + tp*2;
        *(uint32_t*)(g_qTh + off) = (uint32_t)h0 | ((uint32_t)h1 << 16);
        *(uint32_t*)(g_qTl + off) = (uint32_t)l0 | ((uint32_t)l1 << 16);
    }
}

// ---------------------------------------------------------------------------
// K2: S tile [128x128] = (q_i . q_j^T)/8 via HMMA bf16 split; symmetric mirror
// grid (136, 16), 256 threads (8 warps, 2x4), warp tile 64x32
// smem: 4 operand tiles (64KB) then reused as fp32 transpose buffer [128][133]
// ---------------------------------------------------------------------------
#define K2_SMEM (128*133*4)   // 68096 > 64KB operands

__global__ __launch_bounds__(256) void k2_mma()
{
    extern __shared__ char smc[];
    float* tsm = (float*)smc;
    const uint32_t sb = smem_u32(smc);
    const int tid = threadIdx.x, lane = tid & 31, w = tid >> 5;
    const int b = blockIdx.y;
    int jy = 0, rem = blockIdx.x;
    while (rem >= 16 - jy) { rem -= 16 - jy; jy++; }
    const int ix = jy + rem;
    const int i0 = ix * 128, j0 = jy * 128;

    // load 4 operand tiles: A(q rows i0..) hi/lo, B(q rows j0..) hi/lo
    #pragma unroll
    for (int it = 0; it < 16; it++) {
        int idx = it*256 + tid;
        int tile = idx >> 10;
        int r = (idx >> 3) & 127, ch = idx & 7;
        const uint16_t* src = (tile == 0 || tile == 2) ? g_qh : g_ql;
        int grow = (tile < 2) ? (i0 + r) : (j0 + r);
        int dst  = tile * 16384;
        uint4 v = *(const uint4*)(src + ((size_t)(b*TT + grow))*DD + ch*8);
        *(uint4*)(smc + dst + SWZ(r*128 + ch*16)) = v;
    }
    __syncthreads();

    const int wm = w >> 2, wn = w & 3;
    const int arow = lane & 15;
    const int acol = (lane & 16) >> 1;          // 0 or 8
    const int brow = (lane & 7) | ((lane & 16) >> 1);
    const int bcol = lane & 8;                  // 0 or 8

    float d[16][4];
    #pragma unroll
    for (int t = 0; t < 16; t++)
        #pragma unroll
        for (int e = 0; e < 4; e++) d[t][e] = 0.f;

    #pragma unroll
    for (int split = 0; split < 3; split++) {
        const uint32_t Ab = sb + ((split == 2) ? 16384 : 0);
        const uint32_t Bb = sb + ((split == 1) ? 49152 : 32768);
        #pragma unroll
        for (int ks = 0; ks < 4; ks++) {
            uint32_t a[4][4];
            #pragma unroll
            for (int mt = 0; mt < 4; mt++)
                LDSM4(a[mt][0], a[mt][1], a[mt][2], a[mt][3],
                      Ab + SWZ((wm*64 + mt*16 + arow)*128 + (ks*16 + acol)*2));
            uint32_t bb[2][4];
            #pragma unroll
            for (int ng = 0; ng < 2; ng++)
                LDSM4(bb[ng][0], bb[ng][1], bb[ng][2], bb[ng][3],
                      Bb + SWZ((wn*32 + ng*16 + brow)*128 + (ks*16 + bcol)*2));
            #pragma unroll
            for (int mt = 0; mt < 4; mt++)
                #pragma unroll
                for (int nt = 0; nt < 4; nt++)
                    mma_bf16(d[mt*4+nt], a[mt],
                             bb[nt>>1][(nt&1)*2], bb[nt>>1][(nt&1)*2+1]);
        }
    }
    __syncthreads();   // operand smem dead; reuse as transpose buffer

    const int r_i = lane >> 2;
    const int c_j = (lane & 3) * 2;
    float* Sb = g_S + (size_t)b * TT * TT;
    const bool diag = (ix == jy);

    #pragma unroll
    for (int mt = 0; mt < 4; mt++) {
        #pragma unroll
        for (int nt = 0; nt < 4; nt++) {
            float v0 = d[mt*4+nt][0]*0.125f, v1 = d[mt*4+nt][1]*0.125f;
            float v2 = d[mt*4+nt][2]*0.125f, v3 = d[mt*4+nt][3]*0.125f;
            int rl = wm*64 + mt*16 + r_i;
            int cl = wn*32 + nt*8 + c_j;
            *(float2*)(Sb + (size_t)(i0 + rl)*TT + j0 + cl)     = make_float2(v0, v1);
            *(float2*)(Sb + (size_t)(i0 + rl + 8)*TT + j0 + cl) = make_float2(v2, v3);
            if (!diag) {
                tsm[rl*133 + cl] = v0;       tsm[rl*133 + cl + 1] = v1;
                tsm[(rl+8)*133 + cl] = v2;   tsm[(rl+8)*133 + cl + 1] = v3;
            }
        }
    }
    if (!diag) {
        __syncthreads();
        #pragma unroll 4
        for (int it = 0; it < 64; it++) {
            int jl = it*2 + (tid >> 7);
            int il = tid & 127;
            Sb[(size_t)(j0 + jl)*TT + i0 + il] = tsm[il*133 + jl];
        }
    }
}

// ---------------------------------------------------------------------------
// K3: per-row c = max + log(sumexp)
// ---------------------------------------------------------------------------
__global__ __launch_bounds__(256) void k3_stats()
{
    const int n = blockIdx.x * 8 + (threadIdx.x >> 5);
    const int lane = threadIdx.x & 31;
    const float* Sr = g_S + (size_t)n * TT;

    float4 v[16];
    float m = -3.0e38f;
    #pragma unroll
    for (int u = 0; u < 16; u++) {
        v[u] = *(const float4*)(Sr + (size_t)(u*32 + lane) * 4);
        m = fmaxf(m, fmaxf(fmaxf(v[u].x, v[u].y), fmaxf(v[u].z, v[u].w)));
    }
    #pragma unroll
    for (int o = 16; o; o >>= 1) m = fmaxf(m, __shfl_xor_sync(0xffffffffu, m, o));
    float s = 0.f;
    #pragma unroll
    for (int u = 0; u < 16; u++)
        s += __expf(v[u].x - m) + __expf(v[u].y - m) + __expf(v[u].z - m) + __expf(v[u].w - m);
    #pragma unroll
    for (int o = 16; o; o >>= 1) s += __shfl_xor_sync(0xffffffffu, s, o);
    if (lane == 0) g_c[n] = m + __logf(s);
}

// ---------------------------------------------------------------------------
// K4: out = P . q via HMMA; P = exp(S - c_j) built on the fly, bf16 split.
// grid (16 i-tiles, 16 b), 256 threads (8 warps, 4x2), warp tile 32m x 32n
// smem: P hi/lo [128][64] (32KB) + qT hi/lo [64][64] (16KB)
// ---------------------------------------------------------------------------
#define K4_PH 0
#define K4_PL 16384
#define K4_BH 32768
#define K4_BL 40960
#define K4_SMEM 49152

__global__ __launch_bounds__(256) void k4_mma(float* __restrict__ out)
{
    extern __shared__ char smc[];
    const uint32_t sb = smem_u32(smc);
    const int tid = threadIdx.x, lane = tid & 31, w = tid >> 5;
    const int i0 = blockIdx.x * 128, b = blockIdx.y;

    const uint16_t* qTh = g_qTh + (size_t)b * DD * TT;
    const uint16_t* qTl = g_qTl + (size_t)b * DD * TT;
    const float*    Sb  = g_S + ((size_t)b*TT + i0) * TT;
    const float*    cb  = g_c + b * TT;

    const int wm = w >> 1, wn = w & 1;
    const int arow = lane & 15;
    const int acol = (lane & 16) >> 1;
    const int brow = (lane & 7) | ((lane & 16) >> 1);
    const int bcol = lane & 8;

    float d[8][4];
    #pragma unroll
    for (int t = 0; t < 8; t++)
        #pragma unroll
        for (int e = 0; e < 4; e++) d[t][e] = 0.f;

    for (int c = 0; c < 32; c++) {
        const int j0c = c * 64;
        __syncthreads();   // previous mma phase done before overwriting smem
        // qT hi/lo chunk [64 d][64 j]
        #pragma unroll
        for (int it = 0; it < 4; it++) {
            int idx = it*256 + tid;
            int hilo = idx >> 9;
            int rr = (idx >> 3) & 63, ch = idx & 7;
            const uint16_t* src = hilo ? qTl : qTh;
            uint4 v = *(const uint4*)(src + (size_t)rr*TT + j0c + ch*8);
            int dst = hilo ? K4_BL : K4_BH;
            *(uint4*)(smc + dst + SWZ(rr*128 + ch*16)) = v;
        }
        // P = exp(S - c_j) hi/lo [128 i][64 j]
        #pragma unroll
        for (int it = 0; it < 8; it++) {
            int idx = it*256 + tid;
            int r = idx >> 4, cc = idx & 15;
            float4 s4 = *(const float4*)(Sb + (size_t)r*TT + j0c + cc*4);
            float4 c4 = *(const float4*)(cb + j0c + cc*4);
            float p0 = __expf(s4.x - c4.x);
            float p1 = __expf(s4.y - c4.y);
            float p2 = __expf(s4.z - c4.z);
            float p3 = __expf(s4.w - c4.w);
            uint16_t h0,l0,h1,l1,h2,l2,h3,l3;
            bfsplit(p0,h0,l0); bfsplit(p1,h1,l1); bfsplit(p2,h2,l2); bfsplit(p3,h3,l3);
            uint2 uh, ul;
            uh.x = (uint32_t)h0 | ((uint32_t)h1 << 16); uh.y = (uint32_t)h2 | ((uint32_t)h3 << 16);
            ul.x = (uint32_t)l0 | ((uint32_t)l1 << 16); ul.y = (uint32_t)l2 | ((uint32_t)l3 << 16);
            uint32_t off = SWZ(r*128 + cc*8);
            *(uint2*)(smc + K4_PH + off) = uh;
            *(uint2*)(smc + K4_PL + off) = ul;
        }
        __syncthreads();

        #pragma unroll
        for (int split = 0; split < 3; split++) {
            const uint32_t Ab = sb + ((split == 2) ? K4_PL : K4_PH);
            const uint32_t Bb = sb + ((split == 1) ? K4_BL : K4_BH);
            #pragma unroll
            for (int ks = 0; ks < 4; ks++) {
                uint32_t a[2][4];
                #pragma unroll
                for (int mt = 0; mt < 2; mt++)
                    LDSM4(a[mt][0], a[mt][1], a[mt][2], a[mt][3],
                          Ab + SWZ((wm*32 + mt*16 + arow)*128 + (ks*16 + acol)*2));
                uint32_t bb[2][4];
                #pragma unroll
                for (int ng = 0; ng < 2; ng++)
                    LDSM4(bb[ng][0], bb[ng][1], bb[ng][2], bb[ng][3],
                          Bb + SWZ((wn*32 + ng*16 + brow)*128 + (ks*16 + bcol)*2));
                #pragma unroll
                for (int mt = 0; mt < 2; mt++)
                    #pragma unroll
                    for (int nt = 0; nt < 4; nt++)
                        mma_bf16(d[mt*4+nt], a[mt],
                                 bb[nt>>1][(nt&1)*2], bb[nt>>1][(nt&1)*2+1]);
            }
        }
    }

    const int r_i = lane >> 2;
    const int c_j = (lane & 3) * 2;
    #pragma unroll
    for (int mt = 0; mt < 2; mt++) {
        #pragma unroll
        for (int nt = 0; nt < 4; nt++) {
            int row = i0 + wm*32 + mt*16 + r_i;
            int col = wn*32 + nt*8 + c_j;
            *(float2*)(out + ((size_t)b*TT + row)*DD + col) =
                make_float2(d[mt*4+nt][0], d[mt*4+nt][1]);
            *(float2*)(out + ((size_t)b*TT + row + 8)*DD + col) =
                make_float2(d[mt*4+nt][2], d[mt*4+nt][3]);
        }
    }
}

// ---------------------------------------------------------------------------
extern "C" void kernel_launch(void* const* d_in, const int* in_sizes, int n_in,
                              void* d_out, int out_size)
{
    const float* x  = (const float*)d_in[0];
    const float* Wq = (const float*)d_in[1];
    const float* bq = (const float*)d_in[2];
    float* out = (float*)d_out;

    const int smem1 = (64*132 + 64*68 + 64) * 4;

    cudaFuncSetAttribute(k1_proj, cudaFuncAttributeMaxDynamicSharedMemorySize, smem1);
    cudaFuncSetAttribute(k2_mma,  cudaFuncAttributeMaxDynamicSharedMemorySize, K2_SMEM);
    cudaFuncSetAttribute(k4_mma,  cudaFuncAttributeMaxDynamicSharedMemorySize, K4_SMEM);

    k1_proj<<<NN/128, 128, smem1>>>(x, Wq, bq);
    k2_mma<<<dim3(136, BB), 256, K2_SMEM>>>();
    k3_stats<<<NN/8, 256>>>();
    k4_mma<<<dim3(16, BB), 256, K4_SMEM>>>(out);
}

// round 6
// speedup vs baseline: 1.7871x; 1.2869x over previous
#include <cuda_runtime.h>
#include <cuda_bf16.h>
#include <cstdint>
#include <cstddef>

#define TT 2048
#define BB 16
#define DD 64
#define EE 512
#define NN (BB*TT)

// ---------------------------------------------------------------------------
// Global scratch
// ---------------------------------------------------------------------------
__device__ float    g_S[(size_t)BB * TT * TT];   // 256 MB scores S = qq^T/8 (fp32)
__device__ uint16_t g_qh[(size_t)NN * DD];       // q hi  (bf16 bits), row-major [N][64]
__device__ uint16_t g_ql[(size_t)NN * DD];       // q lo
__device__ uint16_t g_qTh[(size_t)NN * DD];      // q^T hi, [b][64][2048]
__device__ uint16_t g_qTl[(size_t)NN * DD];      // q^T lo
__device__ float    g_part[(size_t)NN * 16];     // per-(row, j-tile) exp partial sums
__device__ float    g_c[NN];                     // c = log(rowsumexp)

typedef unsigned long long ull;

// ---------------------------------------------------------------------------
// helpers
// ---------------------------------------------------------------------------
__device__ __forceinline__ uint32_t smem_u32(const void* p) {
    uint32_t a;
    asm("{ .reg .u64 t; cvta.to.shared.u64 t, %1; cvt.u32.u64 %0, t; }" : "=r"(a) : "l"(p));
    return a;
}
#define SWZ(o) ((o) ^ (((o) >> 3) & 0x70))

#define LDSM4(r0,r1,r2,r3,a) \
    asm volatile("ldmatrix.sync.aligned.m8n8.x4.shared.b16 {%0,%1,%2,%3}, [%4];" \
        : "=r"(r0),"=r"(r1),"=r"(r2),"=r"(r3) : "r"(a))

__device__ __forceinline__ void mma_bf16(float* d, const uint32_t* a,
                                         uint32_t b0, uint32_t b1) {
    asm volatile("mma.sync.aligned.m16n8k16.row.col.f32.bf16.bf16.f32 "
        "{%0,%1,%2,%3}, {%4,%5,%6,%7}, {%8,%9}, {%0,%1,%2,%3};"
        : "+f"(d[0]),"+f"(d[1]),"+f"(d[2]),"+f"(d[3])
        : "r"(a[0]),"r"(a[1]),"r"(a[2]),"r"(a[3]), "r"(b0),"r"(b1));
}

#define CPA16(dst, src) \
    asm volatile("cp.async.cg.shared.global [%0], [%1], 16;" :: "r"(dst), "l"(src) : "memory")
#define CP_COMMIT() asm volatile("cp.async.commit_group;" ::: "memory")
#define CP_WAIT1()  asm volatile("cp.async.wait_group 1;" ::: "memory")

// fp32 packed-FFMA helpers (K1)
__device__ __forceinline__ ull pk2(float x, float y) {
    ull r; asm("mov.b64 %0,{%1,%2};" : "=l"(r) : "f"(x), "f"(y)); return r;
}
__device__ __forceinline__ void fma2(ull &d, ull a, ull b) {
    asm("fma.rn.f32x2 %0,%1,%2,%0;" : "+l"(d) : "l"(a), "l"(b));
}
__device__ __forceinline__ void upk(ull v, float &x, float &y) {
    asm("mov.b64 {%0,%1},%2;" : "=f"(x), "=f"(y) : "l"(v));
}
__device__ __forceinline__ void bfsplit(float v, uint16_t &h, uint16_t &l) {
    __nv_bfloat16 hh = __float2bfloat16(v);
    float r = v - __bfloat162float(hh);
    __nv_bfloat16 ll = __float2bfloat16(r);
    h = __bfloat16_as_ushort(hh);
    l = __bfloat16_as_ushort(ll);
}

// ---------------------------------------------------------------------------
// K1: q = x @ Wq + bq  -> bf16 hi/lo row-major + transposed  (FFMA2 core)
// ---------------------------------------------------------------------------
__global__ __launch_bounds__(128) void k1_proj(
    const float* __restrict__ x, const float* __restrict__ Wq,
    const float* __restrict__ bq)
{
    extern __shared__ float sm[];
    float (*xsT)[132] = (float(*)[132])sm;
    float (*ws)[68]   = (float(*)[68])(sm + 64*132);
    float *bs = sm + 64*132 + 64*68;

    const int tid = threadIdx.x;
    const int r0 = blockIdx.x * 128;
    if (tid < 64) bs[tid] = bq[tid];

    const int tx = tid & 7, ty = tid >> 3;
    ull acc[8][4];
    #pragma unroll
    for (int r = 0; r < 8; r++)
        #pragma unroll
        for (int c = 0; c < 4; c++) acc[r][c] = 0ull;

    for (int kc = 0; kc < EE; kc += 64) {
        __syncthreads();
        #pragma unroll
        for (int idx = tid; idx < 1024; idx += 128) {
            int k = idx >> 4, qd = idx & 15;
            ((float4*)&ws[k][0])[qd] = ((const float4*)(Wq + (size_t)(kc + k) * DD))[qd];
        }
        const float* xr = x + (size_t)(r0 + tid) * EE + kc;
        #pragma unroll
        for (int u = 0; u < 16; u++) {
            float4 v = *(const float4*)(xr + u * 4);
            xsT[u*4+0][tid] = v.x; xsT[u*4+1][tid] = v.y;
            xsT[u*4+2][tid] = v.z; xsT[u*4+3][tid] = v.w;
        }
        __syncthreads();
        #pragma unroll 8
        for (int k = 0; k < 64; k++) {
            float4 a0 = *(const float4*)&xsT[k][ty*8];
            float4 a1 = *(const float4*)&xsT[k][ty*8+4];
            float4 b0 = *(const float4*)&ws[k][tx*4];
            float4 b1 = *(const float4*)&ws[k][32 + tx*4];
            ull bb0 = pk2(b0.x,b0.y), bb1 = pk2(b0.z,b0.w);
            ull bb2 = pk2(b1.x,b1.y), bb3 = pk2(b1.z,b1.w);
            float av[8] = {a0.x,a0.y,a0.z,a0.w,a1.x,a1.y,a1.z,a1.w};
            #pragma unroll
            for (int r = 0; r < 8; r++) {
                ull ar = pk2(av[r], av[r]);
                fma2(acc[r][0], ar, bb0); fma2(acc[r][1], ar, bb1);
                fma2(acc[r][2], ar, bb2); fma2(acc[r][3], ar, bb3);
            }
        }
    }
    __syncthreads();
    float (*qt)[132] = (float(*)[132])sm;   // [d][row_local]
    const int b = r0 >> 11;
    const int t0l = r0 & (TT - 1);

    #pragma unroll
    for (int r = 0; r < 8; r++) {
        float f[8];
        upk(acc[r][0], f[0], f[1]); upk(acc[r][1], f[2], f[3]);
        upk(acc[r][2], f[4], f[5]); upk(acc[r][3], f[6], f[7]);
        const int rl = ty*8 + r;
        const int row = r0 + rl;
        float v[8];
        #pragma unroll
        for (int c = 0; c < 4; c++) {
            v[c]   = f[c]   + bs[tx*4 + c];
            v[4+c] = f[4+c] + bs[32 + tx*4 + c];
        }
        #pragma unroll
        for (int c = 0; c < 4; c++) {
            qt[tx*4 + c][rl]      = v[c];
            qt[32 + tx*4 + c][rl] = v[4+c];
        }
        uint16_t h[8], l[8];
        #pragma unroll
        for (int c = 0; c < 8; c++) bfsplit(v[c], h[c], l[c]);
        uint2 uh0, ul0, uh1, ul1;
        uh0.x = (uint32_t)h[0] | ((uint32_t)h[1] << 16); uh0.y = (uint32_t)h[2] | ((uint32_t)h[3] << 16);
        uh1.x = (uint32_t)h[4] | ((uint32_t)h[5] << 16); uh1.y = (uint32_t)h[6] | ((uint32_t)h[7] << 16);
        ul0.x = (uint32_t)l[0] | ((uint32_t)l[1] << 16); ul0.y = (uint32_t)l[2] | ((uint32_t)l[3] << 16);
        ul1.x = (uint32_t)l[4] | ((uint32_t)l[5] << 16); ul1.y = (uint32_t)l[6] | ((uint32_t)l[7] << 16);
        *(uint2*)(g_qh + (size_t)row*DD + tx*4)      = uh0;
        *(uint2*)(g_qh + (size_t)row*DD + 32 + tx*4) = uh1;
        *(uint2*)(g_ql + (size_t)row*DD + tx*4)      = ul0;
        *(uint2*)(g_ql + (size_t)row*DD + 32 + tx*4) = ul1;
    }
    __syncthreads();
    for (int idx = tid; idx < 64*64; idx += 128) {
        int d = idx >> 6, tp = idx & 63;
        float v0 = qt[d][tp*2], v1 = qt[d][tp*2 + 1];
        uint16_t h0, l0, h1, l1;
        bfsplit(v0, h0, l0); bfsplit(v1, h1, l1);
        size_t off = ((size_t)b*DD + d)*TT + t0l + tp*2;
        *(uint32_t*)(g_qTh + off) = (uint32_t)h0 | ((uint32_t)h1 << 16);
        *(uint32_t*)(g_qTl + off) = (uint32_t)l0 | ((uint32_t)l1 << 16);
    }
}

// ---------------------------------------------------------------------------
// K2: S tile [128x128] = (q_i . q_j^T)/8 via HMMA bf16 split; symmetric mirror
// + fused exp partial sums (row & column) -> g_part  (deterministic, no atomics)
// grid (136, 16), 256 threads (8 warps, 2x4), warp tile 64x32
// ---------------------------------------------------------------------------
#define K2_SMEM (128*133*4 + 4*128*4 + 2*128*4)   // 68096 + 2048 + 1024 = 71168

__global__ __launch_bounds__(256) void k2_mma()
{
    extern __shared__ char smc[];
    float* tsm = (float*)smc;                          // [128][133] mirror staging
    float* rowpart = (float*)(smc + 68096);            // [4 wn][128 rows]
    float* colpart = (float*)(smc + 68096 + 2048);     // [2 wm][128 cols]
    const uint32_t sb = smem_u32(smc);
    const int tid = threadIdx.x, lane = tid & 31, w = tid >> 5;
    const int b = blockIdx.y;
    int jy = 0, rem = blockIdx.x;
    while (rem >= 16 - jy) { rem -= 16 - jy; jy++; }
    const int ix = jy + rem;
    const int i0 = ix * 128, j0 = jy * 128;

    // load 4 operand tiles: A(q rows i0..) hi/lo, B(q rows j0..) hi/lo
    #pragma unroll
    for (int it = 0; it < 16; it++) {
        int idx = it*256 + tid;
        int tile = idx >> 10;
        int r = (idx >> 3) & 127, ch = idx & 7;
        const uint16_t* src = (tile == 0 || tile == 2) ? g_qh : g_ql;
        int grow = (tile < 2) ? (i0 + r) : (j0 + r);
        int dst  = tile * 16384;
        uint4 v = *(const uint4*)(src + ((size_t)(b*TT + grow))*DD + ch*8);
        *(uint4*)(smc + dst + SWZ(r*128 + ch*16)) = v;
    }
    __syncthreads();

    const int wm = w >> 2, wn = w & 3;
    const int arow = lane & 15;
    const int acol = (lane & 16) >> 1;
    const int brow = (lane & 7) | ((lane & 16) >> 1);
    const int bcol = lane & 8;

    float d[16][4];
    #pragma unroll
    for (int t = 0; t < 16; t++)
        #pragma unroll
        for (int e = 0; e < 4; e++) d[t][e] = 0.f;

    #pragma unroll
    for (int split = 0; split < 3; split++) {
        const uint32_t Ab = sb + ((split == 2) ? 16384 : 0);
        const uint32_t Bb = sb + ((split == 1) ? 49152 : 32768);
        #pragma unroll
        for (int ks = 0; ks < 4; ks++) {
            uint32_t a[4][4];
            #pragma unroll
            for (int mt = 0; mt < 4; mt++)
                LDSM4(a[mt][0], a[mt][1], a[mt][2], a[mt][3],
                      Ab + SWZ((wm*64 + mt*16 + arow)*128 + (ks*16 + acol)*2));
            uint32_t bb[2][4];
            #pragma unroll
            for (int ng = 0; ng < 2; ng++)
                LDSM4(bb[ng][0], bb[ng][1], bb[ng][2], bb[ng][3],
                      Bb + SWZ((wn*32 + ng*16 + brow)*128 + (ks*16 + bcol)*2));
            #pragma unroll
            for (int mt = 0; mt < 4; mt++)
                #pragma unroll
                for (int nt = 0; nt < 4; nt++)
                    mma_bf16(d[mt*4+nt], a[mt],
                             bb[nt>>1][(nt&1)*2], bb[nt>>1][(nt&1)*2+1]);
        }
    }
    __syncthreads();   // operand smem dead; reuse as transpose/stats buffers

    const int r_i = lane >> 2;
    const int c_j = (lane & 3) * 2;
    float* Sb = g_S + (size_t)b * TT * TT;
    const bool diag = (ix == jy);

    float rp[4][2], cp[4][2];
    #pragma unroll
    for (int t = 0; t < 4; t++) { rp[t][0]=rp[t][1]=0.f; cp[t][0]=cp[t][1]=0.f; }

    #pragma unroll
    for (int mt = 0; mt < 4; mt++) {
        #pragma unroll
        for (int nt = 0; nt < 4; nt++) {
            float v0 = d[mt*4+nt][0]*0.125f, v1 = d[mt*4+nt][1]*0.125f;
            float v2 = d[mt*4+nt][2]*0.125f, v3 = d[mt*4+nt][3]*0.125f;
            float e0 = __expf(v0), e1 = __expf(v1), e2 = __expf(v2), e3 = __expf(v3);
            rp[mt][0] += e0 + e1;  rp[mt][1] += e2 + e3;
            cp[nt][0] += e0 + e2;  cp[nt][1] += e1 + e3;
            int rl = wm*64 + mt*16 + r_i;
            int cl = wn*32 + nt*8 + c_j;
            *(float2*)(Sb + (size_t)(i0 + rl)*TT + j0 + cl)     = make_float2(v0, v1);
            *(float2*)(Sb + (size_t)(i0 + rl + 8)*TT + j0 + cl) = make_float2(v2, v3);
            if (!diag) {
                tsm[rl*133 + cl] = v0;       tsm[rl*133 + cl + 1] = v1;
                tsm[(rl+8)*133 + cl] = v2;   tsm[(rl+8)*133 + cl + 1] = v3;
            }
        }
    }
    // row partials: reduce over lane&3 (same row group)
    #pragma unroll
    for (int mt = 0; mt < 4; mt++) {
        float r0 = rp[mt][0], r1 = rp[mt][1];
        r0 += __shfl_xor_sync(0xffffffffu, r0, 1); r0 += __shfl_xor_sync(0xffffffffu, r0, 2);
        r1 += __shfl_xor_sync(0xffffffffu, r1, 1); r1 += __shfl_xor_sync(0xffffffffu, r1, 2);
        if ((lane & 3) == 0) {
            int rl = wm*64 + mt*16 + r_i;
            rowpart[wn*128 + rl]     = r0;
            rowpart[wn*128 + rl + 8] = r1;
        }
    }
    // column partials: reduce over lane>>2 (same col group)
    #pragma unroll
    for (int nt = 0; nt < 4; nt++) {
        float c0 = cp[nt][0], c1 = cp[nt][1];
        c0 += __shfl_xor_sync(0xffffffffu, c0, 4); c0 += __shfl_xor_sync(0xffffffffu, c0, 8);
        c0 += __shfl_xor_sync(0xffffffffu, c0, 16);
        c1 += __shfl_xor_sync(0xffffffffu, c1, 4); c1 += __shfl_xor_sync(0xffffffffu, c1, 8);
        c1 += __shfl_xor_sync(0xffffffffu, c1, 16);
        if (lane < 4) {
            int cl = wn*32 + nt*8 + lane*2;
            colpart[wm*128 + cl]     = c0;
            colpart[wm*128 + cl + 1] = c1;
        }
    }
    __syncthreads();

    if (tid < 128) {
        float rs = rowpart[tid] + rowpart[128+tid] + rowpart[256+tid] + rowpart[384+tid];
        g_part[((size_t)(b*TT + i0 + tid))*16 + jy] = rs;
        if (!diag) {
            float cs = colpart[tid] + colpart[128+tid];
            g_part[((size_t)(b*TT + j0 + tid))*16 + ix] = cs;
        }
    }
    if (!diag) {
        #pragma unroll 4
        for (int it = 0; it < 64; it++) {
            int jl = it*2 + (tid >> 7);
            int il = tid & 127;
            Sb[(size_t)(j0 + jl)*TT + i0 + il] = tsm[il*133 + jl];
        }
    }
}

// ---------------------------------------------------------------------------
// K3': c[n] = log( sum of 16 partials )   (tiny)
// ---------------------------------------------------------------------------
__global__ __launch_bounds__(256) void k3_logz()
{
    const int n = blockIdx.x * 256 + threadIdx.x;
    const float* p = g_part + (size_t)n * 16;
    float4 a = *(const float4*)(p);
    float4 b = *(const float4*)(p + 4);
    float4 c = *(const float4*)(p + 8);
    float4 e = *(const float4*)(p + 12);
    float s = a.x + a.y + a.z + a.w;
    s += b.x + b.y + b.z + b.w;
    s += c.x + c.y + c.z + c.w;
    s += e.x + e.y + e.z + e.w;
    g_c[n] = logf(s);
}

// ---------------------------------------------------------------------------
// K4: out = P . q via HMMA; P = exp(S - c_j); cp.async double-buffered.
// grid (32 i-tiles of 64, 16 b), 256 threads (8 warps: 4 wm x 2 wn)
// ---------------------------------------------------------------------------
#define S_RAW(buf) ((buf)*16384)
#define QH_OFF(buf) (32768 + (buf)*16384)
#define QL_OFF(buf) (32768 + (buf)*16384 + 8192)
#define P_H 65536
#define P_L 73728
#define C_OFF(buf) (81920 + (buf)*256)
#define K4_SMEM 82432

__global__ __launch_bounds__(256, 2) void k4_mma(float* __restrict__ out)
{
    extern __shared__ char smc[];
    const uint32_t sb = smem_u32(smc);
    const int tid = threadIdx.x, lane = tid & 31, w = tid >> 5;
    const int i0 = blockIdx.x * 64, b = blockIdx.y;

    const uint16_t* qTh = g_qTh + (size_t)b * DD * TT;
    const uint16_t* qTl = g_qTl + (size_t)b * DD * TT;
    const float*    Sb  = g_S + ((size_t)b*TT + i0) * TT;
    const float*    cb  = g_c + b * TT;

    auto prefetch = [&](int c, int buf) {
        const int j0c = c * 64;
        #pragma unroll
        for (int k2 = 0; k2 < 4; k2++) {
            int idx = k2*256 + tid;
            int r = idx >> 4, seg = idx & 15;
            CPA16(sb + S_RAW(buf) + r*256 + seg*16,
                  (const void*)(Sb + (size_t)r*TT + j0c + seg*4));
        }
        #pragma unroll
        for (int k2 = 0; k2 < 2; k2++) {
            int idx = k2*256 + tid;
            int r = idx >> 3, seg = idx & 7;
            CPA16(sb + QH_OFF(buf) + SWZ(r*128 + seg*16),
                  (const void*)(qTh + (size_t)r*TT + j0c + seg*8));
            CPA16(sb + QL_OFF(buf) + SWZ(r*128 + seg*16),
                  (const void*)(qTl + (size_t)r*TT + j0c + seg*8));
        }
        if (tid < 16)
            CPA16(sb + C_OFF(buf) + tid*16, (const void*)(cb + j0c + tid*4));
    };

    prefetch(0, 0); CP_COMMIT();
    prefetch(1, 1); CP_COMMIT();

    const int wm = w >> 1, wn = w & 1;
    const int arow = lane & 15;
    const int acol = (lane & 16) >> 1;
    const int brow = (lane & 7) | ((lane & 16) >> 1);
    const int bcol = lane & 8;

    float d[4][4];
    #pragma unroll
    for (int t = 0; t < 4; t++)
        #pragma unroll
        for (int e = 0; e < 4; e++) d[t][e] = 0.f;

    for (int c = 0; c < 32; c++) {
        const int buf = c & 1;
        CP_WAIT1();
        __syncthreads();
        // build P = exp(s - c_j), split hi/lo into smem
        #pragma unroll
        for (int it = 0; it < 4; it++) {
            int idx = it*256 + tid;
            int r = idx >> 4, cc = idx & 15;
            float4 s4 = *(const float4*)(smc + S_RAW(buf) + r*256 + cc*16);
            float4 c4 = *(const float4*)(smc + C_OFF(buf) + cc*16);
            float p0 = __expf(s4.x - c4.x);
            float p1 = __expf(s4.y - c4.y);
            float p2 = __expf(s4.z - c4.z);
            float p3 = __expf(s4.w - c4.w);
            uint16_t h0,l0,h1,l1,h2,l2,h3,l3;
            bfsplit(p0,h0,l0); bfsplit(p1,h1,l1); bfsplit(p2,h2,l2); bfsplit(p3,h3,l3);
            uint2 uh, ul;
            uh.x = (uint32_t)h0 | ((uint32_t)h1 << 16); uh.y = (uint32_t)h2 | ((uint32_t)h3 << 16);
            ul.x = (uint32_t)l0 | ((uint32_t)l1 << 16); ul.y = (uint32_t)l2 | ((uint32_t)l3 << 16);
            uint32_t off = SWZ(r*128 + cc*8);
            *(uint2*)(smc + P_H + off) = uh;
            *(uint2*)(smc + P_L + off) = ul;
        }
        __syncthreads();
        // mma: warp tile 16 i x 32 d, K = 64 j
        #pragma unroll
        for (int split = 0; split < 3; split++) {
            const uint32_t Ab = sb + ((split == 2) ? P_L : P_H);
            const uint32_t Bb = sb + ((split == 1) ? QL_OFF(buf) : QH_OFF(buf));
            #pragma unroll
            for (int ks = 0; ks < 4; ks++) {
                uint32_t a[4];
                LDSM4(a[0], a[1], a[2], a[3],
                      Ab + SWZ((wm*16 + arow)*128 + (ks*16 + acol)*2));
                uint32_t bb[2][4];
                #pragma unroll
                for (int ng = 0; ng < 2; ng++)
                    LDSM4(bb[ng][0], bb[ng][1], bb[ng][2], bb[ng][3],
                          Bb + SWZ((wn*32 + ng*16 + brow)*128 + (ks*16 + bcol)*2));
                #pragma unroll
                for (int nt = 0; nt < 4; nt++)
                    mma_bf16(d[nt], a, bb[nt>>1][(nt&1)*2], bb[nt>>1][(nt&1)*2+1]);
            }
        }
        __syncthreads();
        if (c + 2 < 32) prefetch(c + 2, buf);
        CP_COMMIT();
    }

    const int r_i = lane >> 2;
    const int c_j = (lane & 3) * 2;
    #pragma unroll
    for (int nt = 0; nt < 4; nt++) {
        int row = i0 + wm*16 + r_i;
        int col = wn*32 + nt*8 + c_j;
        *(float2*)(out + ((size_t)b*TT + row)*DD + col) =
            make_float2(d[nt][0], d[nt][1]);
        *(float2*)(out + ((size_t)b*TT + row + 8)*DD + col) =
            make_float2(d[nt][2], d[nt][3]);
    }
}

// ---------------------------------------------------------------------------
extern "C" void kernel_launch(void* const* d_in, const int* in_sizes, int n_in,
                              void* d_out, int out_size)
{
    const float* x  = (const float*)d_in[0];
    const float* Wq = (const float*)d_in[1];
    const float* bq = (const float*)d_in[2];
    float* out = (float*)d_out;

    const int smem1 = (64*132 + 64*68 + 64) * 4;

    cudaFuncSetAttribute(k1_proj, cudaFuncAttributeMaxDynamicSharedMemorySize, smem1);
    cudaFuncSetAttribute(k2_mma,  cudaFuncAttributeMaxDynamicSharedMemorySize, K2_SMEM);
    cudaFuncSetAttribute(k4_mma,  cudaFuncAttributeMaxDynamicSharedMemorySize, K4_SMEM);

    k1_proj<<<NN/128, 128, smem1>>>(x, Wq, bq);
    k2_mma<<<dim3(136, BB), 256, K2_SMEM>>>();
    k3_logz<<<NN/256, 256>>>();
    k4_mma<<<dim3(TT/64, BB), 256, K4_SMEM>>>(out);
}

// round 7
// speedup vs baseline: 1.8404x; 1.0298x over previous
#include <cuda_runtime.h>
#include <cuda_bf16.h>
#include <cstdint>
#include <cstddef>

#define TT 2048
#define BB 16
#define DD 64
#define EE 512
#define NN (BB*TT)

// ---------------------------------------------------------------------------
// Global scratch (no more g_S!)
// ---------------------------------------------------------------------------
__device__ uint16_t g_qh[(size_t)NN * DD];       // q hi  (bf16 bits), row-major [N][64]
__device__ uint16_t g_ql[(size_t)NN * DD];       // q lo
__device__ uint16_t g_qTh[(size_t)NN * DD];      // q^T hi, [b][64][2048]
__device__ uint16_t g_qTl[(size_t)NN * DD];      // q^T lo
__device__ float    g_part[(size_t)NN * 16];     // per-(row, j-tile) exp partial sums
__device__ float    g_c[NN];                     // c = log(rowsumexp)

typedef unsigned long long ull;

// ---------------------------------------------------------------------------
// helpers
// ---------------------------------------------------------------------------
__device__ __forceinline__ uint32_t smem_u32(const void* p) {
    uint32_t a;
    asm("{ .reg .u64 t; cvta.to.shared.u64 t, %1; cvt.u32.u64 %0, t; }" : "=r"(a) : "l"(p));
    return a;
}
#define SWZ(o) ((o) ^ (((o) >> 3) & 0x70))

#define LDSM4(r0,r1,r2,r3,a) \
    asm volatile("ldmatrix.sync.aligned.m8n8.x4.shared.b16 {%0,%1,%2,%3}, [%4];" \
        : "=r"(r0),"=r"(r1),"=r"(r2),"=r"(r3) : "r"(a))

__device__ __forceinline__ void mma_bf16(float* d, const uint32_t* a,
                                         uint32_t b0, uint32_t b1) {
    asm volatile("mma.sync.aligned.m16n8k16.row.col.f32.bf16.bf16.f32 "
        "{%0,%1,%2,%3}, {%4,%5,%6,%7}, {%8,%9}, {%0,%1,%2,%3};"
        : "+f"(d[0]),"+f"(d[1]),"+f"(d[2]),"+f"(d[3])
        : "r"(a[0]),"r"(a[1]),"r"(a[2]),"r"(a[3]), "r"(b0),"r"(b1));
}

#define CPA16(dst, src) \
    asm volatile("cp.async.cg.shared.global [%0], [%1], 16;" :: "r"(dst), "l"(src) : "memory")
#define CP_COMMIT() asm volatile("cp.async.commit_group;" ::: "memory")
#define CP_WAIT1()  asm volatile("cp.async.wait_group 1;" ::: "memory")

// fp32 packed-FFMA helpers (K1)
__device__ __forceinline__ ull pk2(float x, float y) {
    ull r; asm("mov.b64 %0,{%1,%2};" : "=l"(r) : "f"(x), "f"(y)); return r;
}
__device__ __forceinline__ void fma2(ull &d, ull a, ull b) {
    asm("fma.rn.f32x2 %0,%1,%2,%0;" : "+l"(d) : "l"(a), "l"(b));
}
__device__ __forceinline__ void upk(ull v, float &x, float &y) {
    asm("mov.b64 {%0,%1},%2;" : "=f"(x), "=f"(y) : "l"(v));
}
__device__ __forceinline__ void bfsplit(float v, uint16_t &h, uint16_t &l) {
    __nv_bfloat16 hh = __float2bfloat16(v);
    float r = v - __bfloat162float(hh);
    __nv_bfloat16 ll = __float2bfloat16(r);
    h = __bfloat16_as_ushort(hh);
    l = __bfloat16_as_ushort(ll);
}

// ---------------------------------------------------------------------------
// K1: q = x @ Wq + bq  -> bf16 hi/lo row-major + transposed  (FFMA2 core)
// ---------------------------------------------------------------------------
__global__ __launch_bounds__(128) void k1_proj(
    const float* __restrict__ x, const float* __restrict__ Wq,
    const float* __restrict__ bq)
{
    extern __shared__ float sm[];
    float (*xsT)[132] = (float(*)[132])sm;
    float (*ws)[68]   = (float(*)[68])(sm + 64*132);
    float *bs = sm + 64*132 + 64*68;

    const int tid = threadIdx.x;
    const int r0 = blockIdx.x * 128;
    if (tid < 64) bs[tid] = bq[tid];

    const int tx = tid & 7, ty = tid >> 3;
    ull acc[8][4];
    #pragma unroll
    for (int r = 0; r < 8; r++)
        #pragma unroll
        for (int c = 0; c < 4; c++) acc[r][c] = 0ull;

    for (int kc = 0; kc < EE; kc += 64) {
        __syncthreads();
        #pragma unroll
        for (int idx = tid; idx < 1024; idx += 128) {
            int k = idx >> 4, qd = idx & 15;
            ((float4*)&ws[k][0])[qd] = ((const float4*)(Wq + (size_t)(kc + k) * DD))[qd];
        }
        const float* xr = x + (size_t)(r0 + tid) * EE + kc;
        #pragma unroll
        for (int u = 0; u < 16; u++) {
            float4 v = *(const float4*)(xr + u * 4);
            xsT[u*4+0][tid] = v.x; xsT[u*4+1][tid] = v.y;
            xsT[u*4+2][tid] = v.z; xsT[u*4+3][tid] = v.w;
        }
        __syncthreads();
        #pragma unroll 8
        for (int k = 0; k < 64; k++) {
            float4 a0 = *(const float4*)&xsT[k][ty*8];
            float4 a1 = *(const float4*)&xsT[k][ty*8+4];
            float4 b0 = *(const float4*)&ws[k][tx*4];
            float4 b1 = *(const float4*)&ws[k][32 + tx*4];
            ull bb0 = pk2(b0.x,b0.y), bb1 = pk2(b0.z,b0.w);
            ull bb2 = pk2(b1.x,b1.y), bb3 = pk2(b1.z,b1.w);
            float av[8] = {a0.x,a0.y,a0.z,a0.w,a1.x,a1.y,a1.z,a1.w};
            #pragma unroll
            for (int r = 0; r < 8; r++) {
                ull ar = pk2(av[r], av[r]);
                fma2(acc[r][0], ar, bb0); fma2(acc[r][1], ar, bb1);
                fma2(acc[r][2], ar, bb2); fma2(acc[r][3], ar, bb3);
            }
        }
    }
    __syncthreads();
    float (*qt)[132] = (float(*)[132])sm;   // [d][row_local]
    const int b = r0 >> 11;
    const int t0l = r0 & (TT - 1);

    #pragma unroll
    for (int r = 0; r < 8; r++) {
        float f[8];
        upk(acc[r][0], f[0], f[1]); upk(acc[r][1], f[2], f[3]);
        upk(acc[r][2], f[4], f[5]); upk(acc[r][3], f[6], f[7]);
        const int rl = ty*8 + r;
        const int row = r0 + rl;
        float v[8];
        #pragma unroll
        for (int c = 0; c < 4; c++) {
            v[c]   = f[c]   + bs[tx*4 + c];
            v[4+c] = f[4+c] + bs[32 + tx*4 + c];
        }
        #pragma unroll
        for (int c = 0; c < 4; c++) {
            qt[tx*4 + c][rl]      = v[c];
            qt[32 + tx*4 + c][rl] = v[4+c];
        }
        uint16_t h[8], l[8];
        #pragma unroll
        for (int c = 0; c < 8; c++) bfsplit(v[c], h[c], l[c]);
        uint2 uh0, ul0, uh1, ul1;
        uh0.x = (uint32_t)h[0] | ((uint32_t)h[1] << 16); uh0.y = (uint32_t)h[2] | ((uint32_t)h[3] << 16);
        uh1.x = (uint32_t)h[4] | ((uint32_t)h[5] << 16); uh1.y = (uint32_t)h[6] | ((uint32_t)h[7] << 16);
        ul0.x = (uint32_t)l[0] | ((uint32_t)l[1] << 16); ul0.y = (uint32_t)l[2] | ((uint32_t)l[3] << 16);
        ul1.x = (uint32_t)l[4] | ((uint32_t)l[5] << 16); ul1.y = (uint32_t)l[6] | ((uint32_t)l[7] << 16);
        *(uint2*)(g_qh + (size_t)row*DD + tx*4)      = uh0;
        *(uint2*)(g_qh + (size_t)row*DD + 32 + tx*4) = uh1;
        *(uint2*)(g_ql + (size_t)row*DD + tx*4)      = ul0;
        *(uint2*)(g_ql + (size_t)row*DD + 32 + tx*4) = ul1;
    }
    __syncthreads();
    for (int idx = tid; idx < 64*64; idx += 128) {
        int d = idx >> 6, tp = idx & 63;
        float v0 = qt[d][tp*2], v1 = qt[d][tp*2 + 1];
        uint16_t h0, l0, h1, l1;
        bfsplit(v0, h0, l0); bfsplit(v1, h1, l1);
        size_t off = ((size_t)b*DD + d)*TT + t0l + tp*2;
        *(uint32_t*)(g_qTh + off) = (uint32_t)h0 | ((uint32_t)h1 << 16);
        *(uint32_t*)(g_qTl + off) = (uint32_t)l0 | ((uint32_t)l1 << 16);
    }
}

// ---------------------------------------------------------------------------
// KA: stats only. S tile = (q_i . q_j^T)/8 via HMMA bf16 split; exp partial
// row & column sums -> g_part. NO S writes.  grid (136, 16), 256 threads.
// ---------------------------------------------------------------------------
#define KA_SMEM (65536 + 2048 + 1024)

__global__ __launch_bounds__(256) void ka_stats()
{
    extern __shared__ char smc[];
    float* rowpart = (float*)(smc + 65536);            // [4 wn][128 rows]
    float* colpart = (float*)(smc + 65536 + 2048);     // [2 wm][128 cols]
    const uint32_t sb = smem_u32(smc);
    const int tid = threadIdx.x, lane = tid & 31, w = tid >> 5;
    const int b = blockIdx.y;
    int jy = 0, rem = blockIdx.x;
    while (rem >= 16 - jy) { rem -= 16 - jy; jy++; }
    const int ix = jy + rem;
    const int i0 = ix * 128, j0 = jy * 128;

    #pragma unroll
    for (int it = 0; it < 16; it++) {
        int idx = it*256 + tid;
        int tile = idx >> 10;
        int r = (idx >> 3) & 127, ch = idx & 7;
        const uint16_t* src = (tile == 0 || tile == 2) ? g_qh : g_ql;
        int grow = (tile < 2) ? (i0 + r) : (j0 + r);
        int dst  = tile * 16384;
        uint4 v = *(const uint4*)(src + ((size_t)(b*TT + grow))*DD + ch*8);
        *(uint4*)(smc + dst + SWZ(r*128 + ch*16)) = v;
    }
    __syncthreads();

    const int wm = w >> 2, wn = w & 3;
    const int arow = lane & 15;
    const int acol = (lane & 16) >> 1;
    const int brow = (lane & 7) | ((lane & 16) >> 1);
    const int bcol = lane & 8;

    float d[16][4];
    #pragma unroll
    for (int t = 0; t < 16; t++)
        #pragma unroll
        for (int e = 0; e < 4; e++) d[t][e] = 0.f;

    #pragma unroll
    for (int split = 0; split < 3; split++) {
        const uint32_t Ab = sb + ((split == 2) ? 16384 : 0);
        const uint32_t Bb = sb + ((split == 1) ? 49152 : 32768);
        #pragma unroll
        for (int ks = 0; ks < 4; ks++) {
            uint32_t a[4][4];
            #pragma unroll
            for (int mt = 0; mt < 4; mt++)
                LDSM4(a[mt][0], a[mt][1], a[mt][2], a[mt][3],
                      Ab + SWZ((wm*64 + mt*16 + arow)*128 + (ks*16 + acol)*2));
            uint32_t bb[2][4];
            #pragma unroll
            for (int ng = 0; ng < 2; ng++)
                LDSM4(bb[ng][0], bb[ng][1], bb[ng][2], bb[ng][3],
                      Bb + SWZ((wn*32 + ng*16 + brow)*128 + (ks*16 + bcol)*2));
            #pragma unroll
            for (int mt = 0; mt < 4; mt++)
                #pragma unroll
                for (int nt = 0; nt < 4; nt++)
                    mma_bf16(d[mt*4+nt], a[mt],
                             bb[nt>>1][(nt&1)*2], bb[nt>>1][(nt&1)*2+1]);
        }
    }

    const int r_i = lane >> 2;
    const bool diag = (ix == jy);

    float rp[4][2], cp[4][2];
    #pragma unroll
    for (int t = 0; t < 4; t++) { rp[t][0]=rp[t][1]=0.f; cp[t][0]=cp[t][1]=0.f; }

    #pragma unroll
    for (int mt = 0; mt < 4; mt++) {
        #pragma unroll
        for (int nt = 0; nt < 4; nt++) {
            float e0 = __expf(d[mt*4+nt][0]*0.125f);
            float e1 = __expf(d[mt*4+nt][1]*0.125f);
            float e2 = __expf(d[mt*4+nt][2]*0.125f);
            float e3 = __expf(d[mt*4+nt][3]*0.125f);
            rp[mt][0] += e0 + e1;  rp[mt][1] += e2 + e3;
            cp[nt][0] += e0 + e2;  cp[nt][1] += e1 + e3;
        }
    }
    #pragma unroll
    for (int mt = 0; mt < 4; mt++) {
        float r0 = rp[mt][0], r1 = rp[mt][1];
        r0 += __shfl_xor_sync(0xffffffffu, r0, 1); r0 += __shfl_xor_sync(0xffffffffu, r0, 2);
        r1 += __shfl_xor_sync(0xffffffffu, r1, 1); r1 += __shfl_xor_sync(0xffffffffu, r1, 2);
        if ((lane & 3) == 0) {
            int rl = wm*64 + mt*16 + r_i;
            rowpart[wn*128 + rl]     = r0;
            rowpart[wn*128 + rl + 8] = r1;
        }
    }
    #pragma unroll
    for (int nt = 0; nt < 4; nt++) {
        float c0 = cp[nt][0], c1 = cp[nt][1];
        c0 += __shfl_xor_sync(0xffffffffu, c0, 4); c0 += __shfl_xor_sync(0xffffffffu, c0, 8);
        c0 += __shfl_xor_sync(0xffffffffu, c0, 16);
        c1 += __shfl_xor_sync(0xffffffffu, c1, 4); c1 += __shfl_xor_sync(0xffffffffu, c1, 8);
        c1 += __shfl_xor_sync(0xffffffffu, c1, 16);
        if (lane < 4) {
            int cl = wn*32 + nt*8 + lane*2;
            colpart[wm*128 + cl]     = c0;
            colpart[wm*128 + cl + 1] = c1;
        }
    }
    __syncthreads();

    if (tid < 128) {
        float rs = rowpart[tid] + rowpart[128+tid] + rowpart[256+tid] + rowpart[384+tid];
        g_part[((size_t)(b*TT + i0 + tid))*16 + jy] = rs;
        if (!diag) {
            float cs = colpart[tid] + colpart[128+tid];
            g_part[((size_t)(b*TT + j0 + tid))*16 + ix] = cs;
        }
    }
}

// ---------------------------------------------------------------------------
// K3': c[n] = log( sum of 16 partials )
// ---------------------------------------------------------------------------
__global__ __launch_bounds__(256) void k3_logz()
{
    const int n = blockIdx.x * 256 + threadIdx.x;
    const float* p = g_part + (size_t)n * 16;
    float4 a = *(const float4*)(p);
    float4 b = *(const float4*)(p + 4);
    float4 c = *(const float4*)(p + 8);
    float4 e = *(const float4*)(p + 12);
    float s = a.x + a.y + a.z + a.w;
    s += b.x + b.y + b.z + b.w;
    s += c.x + c.y + c.z + c.w;
    s += e.x + e.y + e.z + e.w;
    g_c[n] = logf(s);
}

// ---------------------------------------------------------------------------
// KB: fused  out[i,:] = sum_j exp(S_ij - c_j) q[j,:], S recomputed via MMA,
// P kept entirely in registers (D-frag -> A-frag repack).
// grid (16 i-tiles of 128, 16 b), 256 threads (8 warps, each m16).
// ---------------------------------------------------------------------------
#define KB_STRIDE 33024
#define QJH(buf) ((buf)*KB_STRIDE)
#define QJL(buf) ((buf)*KB_STRIDE + 8192)
#define QTH(buf) ((buf)*KB_STRIDE + 16384)
#define QTL(buf) ((buf)*KB_STRIDE + 24576)
#define CBUF(buf) ((buf)*KB_STRIDE + 32768)
#define KB_SMEM (2*KB_STRIDE)

__global__ __launch_bounds__(256) void kb_fused(float* __restrict__ out)
{
    extern __shared__ char smc[];
    const uint32_t sb = smem_u32(smc);
    const int tid = threadIdx.x, lane = tid & 31, w = tid >> 5;
    const int i0 = blockIdx.x * 128, b = blockIdx.y;

    const uint16_t* qh  = g_qh  + (size_t)b * TT * DD;
    const uint16_t* ql  = g_ql  + (size_t)b * TT * DD;
    const uint16_t* qTh = g_qTh + (size_t)b * DD * TT;
    const uint16_t* qTl = g_qTl + (size_t)b * DD * TT;
    const float*    cb  = g_c + b * TT;

    // --- stage q_i [128][64] hi/lo into smem, ldmatrix A frags into regs ---
    #pragma unroll
    for (int it = 0; it < 4; it++) {
        int idx = it*256 + tid;           // 1024: 128 rows x 8 segs
        int r = idx >> 3, seg = idx & 7;
        *(uint4*)(smc + SWZ(r*128 + seg*16)) =
            *(const uint4*)(qh + (size_t)(i0 + r)*DD + seg*8);
        *(uint4*)(smc + 16384 + SWZ(r*128 + seg*16)) =
            *(const uint4*)(ql + (size_t)(i0 + r)*DD + seg*8);
    }
    __syncthreads();

    const int arow = lane & 15;
    const int acol = (lane & 16) >> 1;
    uint32_t aqh[4][4], aql[4][4];
    #pragma unroll
    for (int ks = 0; ks < 4; ks++) {
        LDSM4(aqh[ks][0], aqh[ks][1], aqh[ks][2], aqh[ks][3],
              sb + SWZ((w*16 + arow)*128 + (ks*16 + acol)*2));
        LDSM4(aql[ks][0], aql[ks][1], aql[ks][2], aql[ks][3],
              sb + 16384 + SWZ((w*16 + arow)*128 + (ks*16 + acol)*2));
    }
    __syncthreads();

    auto prefetch = [&](int c, int buf) {
        const int j0c = c * 64;
        #pragma unroll
        for (int k2 = 0; k2 < 2; k2++) {
            int idx = k2*256 + tid;       // 512: 64 rows x 8 segs
            int r = idx >> 3, seg = idx & 7;
            CPA16(sb + QJH(buf) + SWZ(r*128 + seg*16),
                  (const void*)(qh + (size_t)(j0c + r)*DD + seg*8));
            CPA16(sb + QJL(buf) + SWZ(r*128 + seg*16),
                  (const void*)(ql + (size_t)(j0c + r)*DD + seg*8));
            CPA16(sb + QTH(buf) + SWZ(r*128 + seg*16),
                  (const void*)(qTh + (size_t)r*TT + j0c + seg*8));
            CPA16(sb + QTL(buf) + SWZ(r*128 + seg*16),
                  (const void*)(qTl + (size_t)r*TT + j0c + seg*8));
        }
        if (tid < 16)
            CPA16(sb + CBUF(buf) + tid*16, (const void*)(cb + j0c + tid*4));
    };

    prefetch(0, 0); CP_COMMIT();
    prefetch(1, 1); CP_COMMIT();

    const int brow = (lane & 7) | ((lane & 16) >> 1);
    const int bcol = lane & 8;

    float o[8][4];
    #pragma unroll
    for (int t = 0; t < 8; t++)
        #pragma unroll
        for (int e = 0; e < 4; e++) o[t][e] = 0.f;

    for (int c = 0; c < 32; c++) {
        const int buf = c & 1;
        CP_WAIT1();
        __syncthreads();

        // ---- MMA1: s[nt] = q_i . q_j^T  (3-split bf16), 16 x 64 per warp ----
        float s[8][4];
        #pragma unroll
        for (int t = 0; t < 8; t++)
            #pragma unroll
            for (int e = 0; e < 4; e++) s[t][e] = 0.f;

        #pragma unroll
        for (int split = 0; split < 3; split++) {
            const uint32_t (*A)[4] = (split == 2) ? aql : aqh;
            const uint32_t Bb = sb + ((split == 1) ? QJL(buf) : QJH(buf));
            #pragma unroll
            for (int ks = 0; ks < 4; ks++) {
                uint32_t bb[4][4];
                #pragma unroll
                for (int ng = 0; ng < 4; ng++)
                    LDSM4(bb[ng][0], bb[ng][1], bb[ng][2], bb[ng][3],
                          Bb + SWZ((ng*16 + brow)*128 + (ks*16 + bcol)*2));
                #pragma unroll
                for (int nt = 0; nt < 8; nt++)
                    mma_bf16(s[nt], A[ks], bb[nt>>1][(nt&1)*2], bb[nt>>1][(nt&1)*2+1]);
            }
        }

        // ---- P = exp(s/8 - c_j), split hi/lo, repack as MMA2 A-fragments ----
        uint32_t ph01[8], ph23[8], pl01[8], pl23[8];
        #pragma unroll
        for (int nt = 0; nt < 8; nt++) {
            float2 cv = *(const float2*)(smc + CBUF(buf) + (nt*8 + (lane&3)*2)*4);
            float p0 = __expf(fmaf(s[nt][0], 0.125f, -cv.x));
            float p1 = __expf(fmaf(s[nt][1], 0.125f, -cv.y));
            float p2 = __expf(fmaf(s[nt][2], 0.125f, -cv.x));
            float p3 = __expf(fmaf(s[nt][3], 0.125f, -cv.y));
            uint16_t h0,l0,h1,l1,h2,l2,h3,l3;
            bfsplit(p0,h0,l0); bfsplit(p1,h1,l1); bfsplit(p2,h2,l2); bfsplit(p3,h3,l3);
            ph01[nt] = (uint32_t)h0 | ((uint32_t)h1 << 16);
            ph23[nt] = (uint32_t)h2 | ((uint32_t)h3 << 16);
            pl01[nt] = (uint32_t)l0 | ((uint32_t)l1 << 16);
            pl23[nt] = (uint32_t)l2 | ((uint32_t)l3 << 16);
        }

        // ---- MMA2: out += P . qT  (A from registers), 16 x 64 per warp ----
        #pragma unroll
        for (int split = 0; split < 3; split++) {
            const uint32_t* p01 = (split == 2) ? pl01 : ph01;
            const uint32_t* p23 = (split == 2) ? pl23 : ph23;
            const uint32_t Bb = sb + ((split == 1) ? QTL(buf) : QTH(buf));
            #pragma unroll
            for (int ks2 = 0; ks2 < 4; ks2++) {
                uint32_t a2[4] = { p01[2*ks2], p23[2*ks2], p01[2*ks2+1], p23[2*ks2+1] };
                uint32_t bb[4][4];
                #pragma unroll
                for (int ng = 0; ng < 4; ng++)
                    LDSM4(bb[ng][0], bb[ng][1], bb[ng][2], bb[ng][3],
                          Bb + SWZ((ng*16 + brow)*128 + (ks2*16 + bcol)*2));
                #pragma unroll
                for (int nt2 = 0; nt2 < 8; nt2++)
                    mma_bf16(o[nt2], a2, bb[nt2>>1][(nt2&1)*2], bb[nt2>>1][(nt2&1)*2+1]);
            }
        }

        __syncthreads();
        if (c + 2 < 32) prefetch(c + 2, buf);
        CP_COMMIT();
    }

    const int g = lane >> 2;
    const int t2 = (lane & 3) * 2;
    #pragma unroll
    for (int nt2 = 0; nt2 < 8; nt2++) {
        int row = i0 + w*16 + g;
        int col = nt2*8 + t2;
        *(float2*)(out + ((size_t)b*TT + row)*DD + col) =
            make_float2(o[nt2][0], o[nt2][1]);
        *(float2*)(out + ((size_t)b*TT + row + 8)*DD + col) =
            make_float2(o[nt2][2], o[nt2][3]);
    }
}

// ---------------------------------------------------------------------------
extern "C" void kernel_launch(void* const* d_in, const int* in_sizes, int n_in,
                              void* d_out, int out_size)
{
    const float* x  = (const float*)d_in[0];
    const float* Wq = (const float*)d_in[1];
    const float* bq = (const float*)d_in[2];
    float* out = (float*)d_out;

    const int smem1 = (64*132 + 64*68 + 64) * 4;

    cudaFuncSetAttribute(k1_proj,  cudaFuncAttributeMaxDynamicSharedMemorySize, smem1);
    cudaFuncSetAttribute(ka_stats, cudaFuncAttributeMaxDynamicSharedMemorySize, KA_SMEM);
    cudaFuncSetAttribute(kb_fused, cudaFuncAttributeMaxDynamicSharedMemorySize, KB_SMEM);

    k1_proj<<<NN/128, 128, smem1>>>(x, Wq, bq);
    ka_stats<<<dim3(136, BB), 256, KA_SMEM>>>();
    k3_logz<<<NN/256, 256>>>();
    kb_fused<<<dim3(TT/128, BB), 256, KB_SMEM>>>(out);
}